// round 13
// baseline (speedup 1.0000x reference)
#include <cuda_runtime.h>
#include <cuda_fp16.h>
#include <math.h>
#include <stdint.h>

// Problem constants
#define BB   32
#define LL   400
#define HH   512
#define NHH  8
#define DHH  64
#define KW   7
#define NCC  4
#define MM   (BB * LL)      // 12800 tokens
#define H3   (3 * HH)       // 1536

// ---------------------------------------------------------------------------
// Scratch
// ---------------------------------------------------------------------------
__device__ __half g_norm_h [MM * HH];
__device__ __half g_dwout_h[MM * HH];
__device__ __half g_qkv_h  [MM * H3];
__device__ __half g_attout_h[MM * HH];
// fp16 weights: pw | qkv | out | ff
#define WT_PW   0
#define WT_QKV  (NCC * HH * HH)
#define WT_OUT  (WT_QKV + H3 * HH)
#define WT_FF   (WT_OUT + HH * HH)
#define WT_TOT  (WT_FF + HH * HH)
__device__ __half g_wth[WT_TOT];

// ---------------------------------------------------------------------------
// helpers
// ---------------------------------------------------------------------------
__device__ __forceinline__ void mma_f16(float* d, const unsigned* a, const unsigned* b) {
    asm volatile(
        "mma.sync.aligned.m16n8k16.row.col.f32.f16.f16.f32 "
        "{%0,%1,%2,%3}, {%4,%5,%6,%7}, {%8,%9}, {%0,%1,%2,%3};\n"
        : "+f"(d[0]), "+f"(d[1]), "+f"(d[2]), "+f"(d[3])
        : "r"(a[0]), "r"(a[1]), "r"(a[2]), "r"(a[3]), "r"(b[0]), "r"(b[1]));
}

__device__ __forceinline__ void cp_async16(void* smem_dst, const void* gsrc) {
    unsigned sa = (unsigned)__cvta_generic_to_shared(smem_dst);
    asm volatile("cp.async.cg.shared.global [%0], [%1], 16;\n" :: "r"(sa), "l"(gsrc));
}

__device__ __forceinline__ void store2(float* p, float a, float b) {
    *(float2*)p = make_float2(a, b);
}
__device__ __forceinline__ void store2(__half* p, float a, float b) {
    *(__half2*)p = __floats2half2_rn(a, b);
}

// ---------------------------------------------------------------------------
// Weight pre-convert to fp16 (one launch).
// ---------------------------------------------------------------------------
__global__ void conv_all_w_kernel(const float* __restrict__ pw,
                                  const float* __restrict__ qkvw,
                                  const float* __restrict__ ow,
                                  const float* __restrict__ ffw,
                                  __half* __restrict__ out) {
    int i = blockIdx.x * blockDim.x + threadIdx.x;
    const int n_pw  = WT_QKV / 4;
    const int n_qkv = (WT_OUT - WT_QKV) / 4;
    const int n_o   = (WT_FF - WT_OUT) / 4;
    const int n_tot = WT_TOT / 4;
    if (i >= n_tot) return;
    const float* src; int off;
    if (i < n_pw)                     { src = pw;   off = i; }
    else if (i < n_pw + n_qkv)        { src = qkvw; off = i - n_pw; }
    else if (i < n_pw + n_qkv + n_o)  { src = ow;   off = i - n_pw - n_qkv; }
    else                              { src = ffw;  off = i - n_pw - n_qkv - n_o; }
    float4 v = ((const float4*)src)[off];
    ((__half2*)out)[i * 2]     = __floats2half2_rn(v.x, v.y);
    ((__half2*)out)[i * 2 + 1] = __floats2half2_rn(v.z, v.w);
}

// ---------------------------------------------------------------------------
// out = x + positional encoding
// ---------------------------------------------------------------------------
__global__ void add_pe_kernel(const float* __restrict__ x, float* __restrict__ out) {
    int idx = blockIdx.x * blockDim.x + threadIdx.x;
    if (idx >= MM * HH) return;
    int h = idx & (HH - 1);
    int l = (idx / HH) % LL;
    float freq = expf(-(float)(h & ~1) * (9.210340371976184f / (float)HH));
    float a = (float)l * freq;
    float pe = (h & 1) ? cosf(a) : sinf(a);
    out[idx] = x[idx] + pe;
}

// ---------------------------------------------------------------------------
// LayerNorm -> fp16 output. One block/row, 128 thr.
// ---------------------------------------------------------------------------
__global__ void ln_h_kernel(const float* __restrict__ in, __half* __restrict__ out,
                            const float* __restrict__ gw, const float* __restrict__ gb) {
    int row = blockIdx.x;
    int t   = threadIdx.x;  // 128
    const float4* p = (const float4*)(in + (size_t)row * HH);
    float4 v = p[t];

    __shared__ float sh[4];

    float s = v.x + v.y + v.z + v.w;
    #pragma unroll
    for (int o = 16; o > 0; o >>= 1) s += __shfl_down_sync(0xffffffffu, s, o);
    if ((t & 31) == 0) sh[t >> 5] = s;
    __syncthreads();
    float mean = (sh[0] + sh[1] + sh[2] + sh[3]) * (1.0f / HH);
    __syncthreads();

    float dx = v.x - mean, dy = v.y - mean, dz = v.z - mean, dw = v.w - mean;
    float q = dx * dx + dy * dy + dz * dz + dw * dw;
    #pragma unroll
    for (int o = 16; o > 0; o >>= 1) q += __shfl_down_sync(0xffffffffu, q, o);
    if ((t & 31) == 0) sh[t >> 5] = q;
    __syncthreads();
    float var  = (sh[0] + sh[1] + sh[2] + sh[3]) * (1.0f / HH);
    float rstd = rsqrtf(var + 1e-5f);

    float4 g4 = ((const float4*)gw)[t];
    float4 b4 = ((const float4*)gb)[t];
    float ox = dx * rstd * g4.x + b4.x;
    float oy = dy * rstd * g4.y + b4.y;
    float oz = dz * rstd * g4.z + b4.z;
    float ow = dw * rstd * g4.w + b4.w;
    __half2* o2 = (__half2*)(out + (size_t)row * HH);
    o2[t * 2]     = __floats2half2_rn(ox, oy);
    o2[t * 2 + 1] = __floats2half2_rn(oz, ow);
}

// ---------------------------------------------------------------------------
// Fused LayerNorm + depthwise conv (K=7, pad 3) -> fp16 output.
// ---------------------------------------------------------------------------
#define CTILE 16
#define CHALO 3
#define CROWS (CTILE + 2 * CHALO)   // 22

__global__ void __launch_bounds__(256)
ln_dwconv_kernel(const float* __restrict__ in, __half* __restrict__ dwout,
                 const float* __restrict__ gw, const float* __restrict__ gb,
                 const float* __restrict__ w, const float* __restrict__ bias) {
    __shared__ float sm[CROWS * HH];

    int b    = blockIdx.x;
    int t0   = blockIdx.y * CTILE;
    int tid  = threadIdx.x;
    int warp = tid >> 5;
    int lane = tid & 31;

    for (int rr = warp; rr < CROWS; rr += 8) {
        int l = t0 - CHALO + rr;
        if (l < 0 || l >= LL) {
            #pragma unroll
            for (int j = 0; j < 4; j++)
                *(float4*)&sm[rr * HH + lane * 4 + j * 128] = make_float4(0.f, 0.f, 0.f, 0.f);
            continue;
        }
        const float4* p = (const float4*)(in + ((size_t)(b * LL + l)) * HH);
        float4 v[4];
        float s = 0.0f;
        #pragma unroll
        for (int j = 0; j < 4; j++) {
            v[j] = p[lane + j * 32];
            s += v[j].x + v[j].y + v[j].z + v[j].w;
        }
        #pragma unroll
        for (int o = 16; o > 0; o >>= 1) s += __shfl_xor_sync(0xffffffffu, s, o);
        float mean = s * (1.0f / HH);

        float q = 0.0f;
        #pragma unroll
        for (int j = 0; j < 4; j++) {
            float dx = v[j].x - mean, dy = v[j].y - mean;
            float dz = v[j].z - mean, dw = v[j].w - mean;
            q += dx * dx + dy * dy + dz * dz + dw * dw;
        }
        #pragma unroll
        for (int o = 16; o > 0; o >>= 1) q += __shfl_xor_sync(0xffffffffu, q, o);
        float rstd = rsqrtf(q * (1.0f / HH) + 1e-5f);

        #pragma unroll
        for (int j = 0; j < 4; j++) {
            int c = lane * 4 + j * 128;
            float4 g4 = *(const float4*)&gw[c];
            float4 b4 = *(const float4*)&gb[c];
            float4 o4;
            o4.x = (v[j].x - mean) * rstd * g4.x + b4.x;
            o4.y = (v[j].y - mean) * rstd * g4.y + b4.y;
            o4.z = (v[j].z - mean) * rstd * g4.z + b4.z;
            o4.w = (v[j].w - mean) * rstd * g4.w + b4.w;
            *(float4*)&sm[rr * HH + c] = o4;
        }
    }
    __syncthreads();

    int c0 = tid * 2;
    float wr0[KW], wr1[KW];
    #pragma unroll
    for (int k = 0; k < KW; k++) {
        wr0[k] = w[c0 * KW + k];
        wr1[k] = w[(c0 + 1) * KW + k];
    }
    float bi0 = bias[c0], bi1 = bias[c0 + 1];

    #pragma unroll 4
    for (int r = 0; r < CTILE; r++) {
        float a0 = bi0, a1 = bi1;
        #pragma unroll
        for (int k = 0; k < KW; k++) {
            float2 x = *(const float2*)&sm[(r + k) * HH + c0];
            a0 += x.x * wr0[k];
            a1 += x.y * wr1[k];
        }
        *(__half2*)&dwout[((size_t)(b * LL + t0 + r)) * HH + c0] =
            __floats2half2_rn(a0, a1);
    }
}

// ---------------------------------------------------------------------------
// fp16 tensor-core GEMM: BM=128, BN=64, BK=32 halves, 3-stage cp.async.
// 256 threads (8 warps, 4x2), warp tile 32x32, m16n8k16, fp32 accumulate.
// 3 CTAs/SM (regs capped by launch_bounds) for wave balance:
// grid 800 on 444 slots = 2 waves @ 90% util (vs 400/296 = 68%).
// ---------------------------------------------------------------------------
#define GH_ROWW   20
#define GH_A_SS   (128 * GH_ROWW)                   // A words per stage
#define GH_B_SS   (64 * GH_ROWW)                    // B words per stage
#define GH_SS     (GH_A_SS + GH_B_SS)
#define GH_NSTG   3
#define GEMM_SMEM (GH_NSTG * GH_SS * 4)             // 46080 bytes

template <bool RELU, bool RES, typename TOUT>
__global__ void __launch_bounds__(256, 3)
gemm_f16_kernel(const __half* __restrict__ A, const __half* __restrict__ W,
                const float* __restrict__ bias, const float* __restrict__ R,
                TOUT* __restrict__ C, int Md, int Nd, int Kd) {
    extern __shared__ unsigned gsm[];

    int tid  = threadIdx.x;
    int m0   = blockIdx.y * 128;
    int n0   = blockIdx.x * 64;
    int warp = tid >> 5;
    int lane = tid & 31;
    int wm   = (warp >> 1) * 32;   // 0,32,64,96
    int wn   = (warp & 1) * 32;    // 0,32
    int lg   = lane >> 2;
    int lq   = lane & 3;

    int lrow = tid >> 2;           // 0..63
    int lchunk = (tid & 3);
    int swA0 = lrow * GH_ROWW + lchunk * 4;
    int swA1 = (64 + lrow) * GH_ROWW + lchunk * 4;
    int swB  = GH_A_SS + lrow * GH_ROWW + lchunk * 4;

    const __half* Ag0 = &A[(size_t)(m0 + lrow)      * Kd + lchunk * 8];
    const __half* Ag1 = &A[(size_t)(m0 + 64 + lrow) * Kd + lchunk * 8];
    const __half* Wg  = &W[(size_t)(n0 + lrow)      * Kd + lchunk * 8];

    float acc[2][4][4];
    #pragma unroll
    for (int i = 0; i < 2; i++)
        #pragma unroll
        for (int j = 0; j < 4; j++)
            #pragma unroll
            for (int r = 0; r < 4; r++) acc[i][j][r] = 0.0f;

    #define LOAD_STAGE(s, ko)                                                   \
    {                                                                           \
        unsigned* S_ = gsm + (s) * GH_SS;                                       \
        cp_async16(S_ + swA0, Ag0 + (ko));                                      \
        cp_async16(S_ + swA1, Ag1 + (ko));                                      \
        cp_async16(S_ + swB,  Wg  + (ko));                                      \
        asm volatile("cp.async.commit_group;\n");                               \
    }

    int nit = Kd >> 5;
    LOAD_STAGE(0, 0);
    if (nit > 1) LOAD_STAGE(1, 32);

    for (int it = 0; it < nit; it++) {
        if (it + 1 < nit)
            asm volatile("cp.async.wait_group 1;\n");
        else
            asm volatile("cp.async.wait_group 0;\n");
        __syncthreads();
        if (it + 2 < nit) LOAD_STAGE((it + 2) % GH_NSTG, (it + 2) << 5);

        int cur = it % GH_NSTG;
        const unsigned* Asc = gsm + cur * GH_SS;
        const unsigned* Bsc = Asc + GH_A_SS;

        #pragma unroll
        for (int ks = 0; ks < 2; ks++) {
            int kb = ks * 8;
            unsigned af[2][4], bf[4][2];
            #pragma unroll
            for (int mt = 0; mt < 2; mt++) {
                int mr = wm + mt * 16 + lg;
                af[mt][0] = Asc[mr * GH_ROWW + kb + lq];
                af[mt][1] = Asc[(mr + 8) * GH_ROWW + kb + lq];
                af[mt][2] = Asc[mr * GH_ROWW + kb + lq + 4];
                af[mt][3] = Asc[(mr + 8) * GH_ROWW + kb + lq + 4];
            }
            #pragma unroll
            for (int nt = 0; nt < 4; nt++) {
                int nr = wn + nt * 8 + lg;
                bf[nt][0] = Bsc[nr * GH_ROWW + kb + lq];
                bf[nt][1] = Bsc[nr * GH_ROWW + kb + lq + 4];
            }
            #pragma unroll
            for (int mt = 0; mt < 2; mt++)
                #pragma unroll
                for (int nt = 0; nt < 4; nt++)
                    mma_f16(acc[mt][nt], af[mt], bf[nt]);
        }
    }
    #undef LOAD_STAGE

    #pragma unroll
    for (int mt = 0; mt < 2; mt++) {
        #pragma unroll
        for (int half = 0; half < 2; half++) {
            int m = m0 + wm + mt * 16 + lg + half * 8;
            #pragma unroll
            for (int nt = 0; nt < 4; nt++) {
                int n = n0 + wn + nt * 8 + 2 * lq;
                float v0 = acc[mt][nt][half * 2 + 0] + bias[n];
                float v1 = acc[mt][nt][half * 2 + 1] + bias[n + 1];
                if (RELU) { v0 = fmaxf(v0, 0.0f); v1 = fmaxf(v1, 0.0f); }
                if (RES)  { v0 += R[(size_t)m * Nd + n]; v1 += R[(size_t)m * Nd + n + 1]; }
                store2(&C[(size_t)m * Nd + n], v0, v1);
            }
        }
    }
}

// ---------------------------------------------------------------------------
// Fused flash attention, fp16 MMA (m16n8k16), online softmax.
// ---------------------------------------------------------------------------
#define FW 36

__global__ void __launch_bounds__(128)
flash_kernel(const __half* __restrict__ qkv, const int* __restrict__ mask,
             __half* __restrict__ attout) {
    __shared__ unsigned Qs [64 * FW];
    __shared__ unsigned KPs[64 * FW];
    __shared__ unsigned Vst[64 * FW];
    __shared__ int msk[64];

    int bh = blockIdx.x;
    int b  = bh >> 3;
    int h  = bh & 7;
    int q0 = blockIdx.y * 64;

    int tid  = threadIdx.x;
    int warp = tid >> 5;
    int lane = tid & 31;
    int wr   = warp * 16;
    int lg   = lane >> 2;
    int lq   = lane & 3;

    const __half2 qsc = __float2half2_rn(0.125f);

    for (int i = tid; i < 512; i += 128) {
        int r  = i >> 3;
        int cw = (i & 7) * 4;
        int qr = q0 + r; if (qr > LL - 1) qr = LL - 1;
        uint4 v = *(const uint4*)&qkv[((size_t)(b * LL + qr)) * H3 + h * DHH + cw * 2];
        __half2 h0 = __hmul2(*(__half2*)&v.x, qsc);
        __half2 h1 = __hmul2(*(__half2*)&v.y, qsc);
        __half2 h2 = __hmul2(*(__half2*)&v.z, qsc);
        __half2 h3 = __hmul2(*(__half2*)&v.w, qsc);
        uint4 sv;
        sv.x = *(unsigned*)&h0; sv.y = *(unsigned*)&h1;
        sv.z = *(unsigned*)&h2; sv.w = *(unsigned*)&h3;
        *(uint4*)&Qs[r * FW + cw] = sv;
    }

    float oacc[8][4];
    #pragma unroll
    for (int nt = 0; nt < 8; nt++)
        #pragma unroll
        for (int r2 = 0; r2 < 4; r2++) oacc[nt][r2] = 0.0f;
    float m0 = -1e30f, m1 = -1e30f, l0 = 0.0f, l1 = 0.0f;

    for (int kt = 0; kt < LL; kt += 64) {
        __syncthreads();

        for (int i = tid; i < 512; i += 128) {
            int r  = i >> 3;
            int cw = (i & 7) * 4;
            int kr = kt + r; if (kr > LL - 1) kr = LL - 1;
            const __half* base = &qkv[((size_t)(b * LL + kr)) * H3 + h * DHH + cw * 2];
            uint4 kv = *(const uint4*)(base + HH);
            *(uint4*)&KPs[r * FW + cw] = kv;
            uint4 vv = *(const uint4*)(base + 2 * HH);
            const __half* vh = (const __half*)&vv;
            __half* Vh = (__half*)Vst;
            #pragma unroll
            for (int j = 0; j < 8; j++)
                Vh[(cw * 2 + j) * (FW * 2) + r] = vh[j];
        }
        if (tid < 64) msk[tid] = (kt + tid < LL) ? mask[b * LL + kt + tid] : 0;
        __syncthreads();

        float sacc[8][4];
        #pragma unroll
        for (int nt = 0; nt < 8; nt++)
            #pragma unroll
            for (int r2 = 0; r2 < 4; r2++) sacc[nt][r2] = 0.0f;

        #pragma unroll
        for (int ks = 0; ks < 4; ks++) {
            int kb = ks * 8;
            unsigned af[4];
            af[0] = Qs[(wr + lg)     * FW + kb + lq];
            af[1] = Qs[(wr + lg + 8) * FW + kb + lq];
            af[2] = Qs[(wr + lg)     * FW + kb + lq + 4];
            af[3] = Qs[(wr + lg + 8) * FW + kb + lq + 4];
            #pragma unroll
            for (int nt = 0; nt < 8; nt++) {
                unsigned bf[2];
                bf[0] = KPs[(nt * 8 + lg) * FW + kb + lq];
                bf[1] = KPs[(nt * 8 + lg) * FW + kb + lq + 4];
                mma_f16(sacc[nt], af, bf);
            }
        }

        float rmax0 = -1e30f, rmax1 = -1e30f;
        #pragma unroll
        for (int nt = 0; nt < 8; nt++) {
            #pragma unroll
            for (int j = 0; j < 2; j++) {
                int kl = nt * 8 + 2 * lq + j;
                bool ok = (kt + kl < LL) && (msk[kl] > 0);
                if (!ok) { sacc[nt][j] = -1e30f; sacc[nt][2 + j] = -1e30f; }
                rmax0 = fmaxf(rmax0, sacc[nt][j]);
                rmax1 = fmaxf(rmax1, sacc[nt][2 + j]);
            }
        }
        #pragma unroll
        for (int o = 1; o <= 2; o <<= 1) {
            rmax0 = fmaxf(rmax0, __shfl_xor_sync(0xffffffffu, rmax0, o));
            rmax1 = fmaxf(rmax1, __shfl_xor_sync(0xffffffffu, rmax1, o));
        }

        float m0n = fmaxf(m0, rmax0);
        float m1n = fmaxf(m1, rmax1);
        float alpha0 = __expf(m0 - m0n);
        float alpha1 = __expf(m1 - m1n);
        m0 = m0n; m1 = m1n;

        float rs0 = 0.0f, rs1 = 0.0f;
        #pragma unroll
        for (int nt = 0; nt < 8; nt++) {
            #pragma unroll
            for (int j = 0; j < 2; j++) {
                float p0 = __expf(sacc[nt][j] - m0);
                float p1 = __expf(sacc[nt][2 + j] - m1);
                sacc[nt][j] = p0;     rs0 += p0;
                sacc[nt][2 + j] = p1; rs1 += p1;
            }
        }
        #pragma unroll
        for (int o = 1; o <= 2; o <<= 1) {
            rs0 += __shfl_xor_sync(0xffffffffu, rs0, o);
            rs1 += __shfl_xor_sync(0xffffffffu, rs1, o);
        }
        l0 = l0 * alpha0 + rs0;
        l1 = l1 * alpha1 + rs1;

        #pragma unroll
        for (int nt = 0; nt < 8; nt++) {
            oacc[nt][0] *= alpha0; oacc[nt][1] *= alpha0;
            oacc[nt][2] *= alpha1; oacc[nt][3] *= alpha1;
        }

        __syncthreads();

        #pragma unroll
        for (int nt = 0; nt < 8; nt++) {
            __half2 p01 = __floats2half2_rn(sacc[nt][0], sacc[nt][1]);
            __half2 p23 = __floats2half2_rn(sacc[nt][2], sacc[nt][3]);
            KPs[(wr + lg)     * FW + nt * 4 + lq] = *(unsigned*)&p01;
            KPs[(wr + lg + 8) * FW + nt * 4 + lq] = *(unsigned*)&p23;
        }
        __syncwarp();

        #pragma unroll
        for (int ks = 0; ks < 4; ks++) {
            int kb = ks * 8;
            unsigned af[4];
            af[0] = KPs[(wr + lg)     * FW + kb + lq];
            af[1] = KPs[(wr + lg + 8) * FW + kb + lq];
            af[2] = KPs[(wr + lg)     * FW + kb + lq + 4];
            af[3] = KPs[(wr + lg + 8) * FW + kb + lq + 4];
            #pragma unroll
            for (int nt = 0; nt < 8; nt++) {
                unsigned bf[2];
                bf[0] = Vst[(nt * 8 + lg) * FW + kb + lq];
                bf[1] = Vst[(nt * 8 + lg) * FW + kb + lq + 4];
                mma_f16(oacc[nt], af, bf);
            }
        }
    }

    float inv0 = 1.0f / fmaxf(l0, 1e-30f);
    float inv1 = 1.0f / fmaxf(l1, 1e-30f);
    int r0 = q0 + wr + lg;
    int r1 = r0 + 8;
    #pragma unroll
    for (int nt = 0; nt < 8; nt++) {
        int c = nt * 8 + 2 * lq;
        if (r0 < LL)
            *(__half2*)&attout[((size_t)(b * LL + r0)) * HH + h * DHH + c] =
                __floats2half2_rn(oacc[nt][0] * inv0, oacc[nt][1] * inv0);
        if (r1 < LL)
            *(__half2*)&attout[((size_t)(b * LL + r1)) * HH + h * DHH + c] =
                __floats2half2_rn(oacc[nt][2] * inv1, oacc[nt][3] * inv1);
    }
}

// ---------------------------------------------------------------------------
// Launch
// ---------------------------------------------------------------------------
extern "C" void kernel_launch(void* const* d_in, const int* in_sizes, int n_in,
                              void* d_out, int out_size) {
    const float* x         = (const float*)d_in[0];
    const int*   mask      = (const int*)  d_in[1];
    const float* conv_ln_g = (const float*)d_in[2];
    const float* conv_ln_b = (const float*)d_in[3];
    const float* dw_w      = (const float*)d_in[4];
    const float* dw_b      = (const float*)d_in[5];
    const float* pw_w      = (const float*)d_in[6];
    const float* pw_b      = (const float*)d_in[7];
    const float* att_ln_g  = (const float*)d_in[8];
    const float* att_ln_b  = (const float*)d_in[9];
    const float* qkv_w     = (const float*)d_in[10];
    const float* qkv_b     = (const float*)d_in[11];
    const float* out_w     = (const float*)d_in[12];
    const float* out_b     = (const float*)d_in[13];
    const float* ff_ln_g   = (const float*)d_in[14];
    const float* ff_ln_b   = (const float*)d_in[15];
    const float* ff_w      = (const float*)d_in[16];
    const float* ff_b      = (const float*)d_in[17];
    float* out = (float*)d_out;

    __half *normh, *dwouth, *qkvh, *attouth, *wth;
    cudaGetSymbolAddress((void**)&normh,   g_norm_h);
    cudaGetSymbolAddress((void**)&dwouth,  g_dwout_h);
    cudaGetSymbolAddress((void**)&qkvh,    g_qkv_h);
    cudaGetSymbolAddress((void**)&attouth, g_attout_h);
    cudaGetSymbolAddress((void**)&wth,     g_wth);

    cudaFuncSetAttribute(gemm_f16_kernel<true, true, float>,
                         cudaFuncAttributeMaxDynamicSharedMemorySize, GEMM_SMEM);
    cudaFuncSetAttribute(gemm_f16_kernel<false, false, __half>,
                         cudaFuncAttributeMaxDynamicSharedMemorySize, GEMM_SMEM);
    cudaFuncSetAttribute(gemm_f16_kernel<false, true, float>,
                         cudaFuncAttributeMaxDynamicSharedMemorySize, GEMM_SMEM);

    const int elems = MM * HH;

    conv_all_w_kernel<<<(WT_TOT / 4 + 255) / 256, 256>>>(pw_w, qkv_w, out_w, ff_w, wth);

    add_pe_kernel<<<(elems + 255) / 256, 256>>>(x, out);

    for (int i = 0; i < NCC; i++) {
        ln_dwconv_kernel<<<dim3(BB, LL / CTILE), 256>>>(
            out, dwouth, conv_ln_g + i * HH, conv_ln_b + i * HH,
            dw_w + i * HH * KW, dw_b + i * HH);
        gemm_f16_kernel<true, true, float><<<dim3(HH / 64, MM / 128), 256, GEMM_SMEM>>>(
            dwouth, wth + WT_PW + (size_t)i * HH * HH, pw_b + i * HH, out, out, MM, HH, HH);
    }

    ln_h_kernel<<<MM, 128>>>(out, normh, att_ln_g, att_ln_b);
    gemm_f16_kernel<false, false, __half><<<dim3(H3 / 64, MM / 128), 256, GEMM_SMEM>>>(
        normh, wth + WT_QKV, qkv_b, (const float*)nullptr, qkvh, MM, H3, HH);

    flash_kernel<<<dim3(BB * NHH, (LL + 63) / 64), 128>>>(qkvh, mask, attouth);

    gemm_f16_kernel<false, true, float><<<dim3(HH / 64, MM / 128), 256, GEMM_SMEM>>>(
        attouth, wth + WT_OUT, out_b, out, out, MM, HH, HH);

    ln_h_kernel<<<MM, 128>>>(out, normh, ff_ln_g, ff_ln_b);
    gemm_f16_kernel<true, true, float><<<dim3(HH / 64, MM / 128), 256, GEMM_SMEM>>>(
        normh, wth + WT_FF, ff_b, out, out, MM, HH, HH);
}

// round 14
// speedup vs baseline: 1.0788x; 1.0788x over previous
#include <cuda_runtime.h>
#include <cuda_fp16.h>
#include <math.h>
#include <stdint.h>

// Problem constants
#define BB   32
#define LL   400
#define HH   512
#define NHH  8
#define DHH  64
#define KW   7
#define NCC  4
#define MM   (BB * LL)      // 12800 tokens
#define H3   (3 * HH)       // 1536

// ---------------------------------------------------------------------------
// Scratch
// ---------------------------------------------------------------------------
__device__ __half g_norm_h [MM * HH];
__device__ __half g_dwout_h[MM * HH];
__device__ __half g_qkv_h  [MM * H3];
__device__ __half g_attout_h[MM * HH];
// fp16 weights: pw | qkv | out | ff
#define WT_PW   0
#define WT_QKV  (NCC * HH * HH)
#define WT_OUT  (WT_QKV + H3 * HH)
#define WT_FF   (WT_OUT + HH * HH)
#define WT_TOT  (WT_FF + HH * HH)
__device__ __half g_wth[WT_TOT];

// ---------------------------------------------------------------------------
// helpers
// ---------------------------------------------------------------------------
__device__ __forceinline__ void mma_f16(float* d, const unsigned* a, const unsigned* b) {
    asm volatile(
        "mma.sync.aligned.m16n8k16.row.col.f32.f16.f16.f32 "
        "{%0,%1,%2,%3}, {%4,%5,%6,%7}, {%8,%9}, {%0,%1,%2,%3};\n"
        : "+f"(d[0]), "+f"(d[1]), "+f"(d[2]), "+f"(d[3])
        : "r"(a[0]), "r"(a[1]), "r"(a[2]), "r"(a[3]), "r"(b[0]), "r"(b[1]));
}

__device__ __forceinline__ void cp_async16(void* smem_dst, const void* gsrc) {
    unsigned sa = (unsigned)__cvta_generic_to_shared(smem_dst);
    asm volatile("cp.async.cg.shared.global [%0], [%1], 16;\n" :: "r"(sa), "l"(gsrc));
}

__device__ __forceinline__ void store2(float* p, float a, float b) {
    *(float2*)p = make_float2(a, b);
}
__device__ __forceinline__ void store2(__half* p, float a, float b) {
    *(__half2*)p = __floats2half2_rn(a, b);
}

// ---------------------------------------------------------------------------
// Weight pre-convert to fp16 (one launch).
// ---------------------------------------------------------------------------
__global__ void conv_all_w_kernel(const float* __restrict__ pw,
                                  const float* __restrict__ qkvw,
                                  const float* __restrict__ ow,
                                  const float* __restrict__ ffw,
                                  __half* __restrict__ out) {
    int i = blockIdx.x * blockDim.x + threadIdx.x;
    const int n_pw  = WT_QKV / 4;
    const int n_qkv = (WT_OUT - WT_QKV) / 4;
    const int n_o   = (WT_FF - WT_OUT) / 4;
    const int n_tot = WT_TOT / 4;
    if (i >= n_tot) return;
    const float* src; int off;
    if (i < n_pw)                     { src = pw;   off = i; }
    else if (i < n_pw + n_qkv)        { src = qkvw; off = i - n_pw; }
    else if (i < n_pw + n_qkv + n_o)  { src = ow;   off = i - n_pw - n_qkv; }
    else                              { src = ffw;  off = i - n_pw - n_qkv - n_o; }
    float4 v = ((const float4*)src)[off];
    ((__half2*)out)[i * 2]     = __floats2half2_rn(v.x, v.y);
    ((__half2*)out)[i * 2 + 1] = __floats2half2_rn(v.z, v.w);
}

// ---------------------------------------------------------------------------
// LayerNorm -> fp16 output. One block/row, 128 thr.
// ---------------------------------------------------------------------------
__global__ void ln_h_kernel(const float* __restrict__ in, __half* __restrict__ out,
                            const float* __restrict__ gw, const float* __restrict__ gb) {
    int row = blockIdx.x;
    int t   = threadIdx.x;  // 128
    const float4* p = (const float4*)(in + (size_t)row * HH);
    float4 v = p[t];

    __shared__ float sh[4];

    float s = v.x + v.y + v.z + v.w;
    #pragma unroll
    for (int o = 16; o > 0; o >>= 1) s += __shfl_down_sync(0xffffffffu, s, o);
    if ((t & 31) == 0) sh[t >> 5] = s;
    __syncthreads();
    float mean = (sh[0] + sh[1] + sh[2] + sh[3]) * (1.0f / HH);
    __syncthreads();

    float dx = v.x - mean, dy = v.y - mean, dz = v.z - mean, dw = v.w - mean;
    float q = dx * dx + dy * dy + dz * dz + dw * dw;
    #pragma unroll
    for (int o = 16; o > 0; o >>= 1) q += __shfl_down_sync(0xffffffffu, q, o);
    if ((t & 31) == 0) sh[t >> 5] = q;
    __syncthreads();
    float var  = (sh[0] + sh[1] + sh[2] + sh[3]) * (1.0f / HH);
    float rstd = rsqrtf(var + 1e-5f);

    float4 g4 = ((const float4*)gw)[t];
    float4 b4 = ((const float4*)gb)[t];
    float ox = dx * rstd * g4.x + b4.x;
    float oy = dy * rstd * g4.y + b4.y;
    float oz = dz * rstd * g4.z + b4.z;
    float ow = dw * rstd * g4.w + b4.w;
    __half2* o2 = (__half2*)(out + (size_t)row * HH);
    o2[t * 2]     = __floats2half2_rn(ox, oy);
    o2[t * 2 + 1] = __floats2half2_rn(oz, ow);
}

// ---------------------------------------------------------------------------
// Fused (optional PE-add) + LayerNorm + depthwise conv (K=7, pad 3).
// ADDPE: input is raw x; compute x+pe on the fly, write fp32 residual stream
// `resid` for core rows (each row core in exactly one block), LN from x+pe.
// Output: fp16 dwout (feeds pointwise GEMM A).
// ---------------------------------------------------------------------------
#define CTILE 16
#define CHALO 3
#define CROWS (CTILE + 2 * CHALO)   // 22

template <bool ADDPE>
__global__ void __launch_bounds__(256)
ln_dwconv_kernel(const float* __restrict__ in, float* __restrict__ resid,
                 __half* __restrict__ dwout,
                 const float* __restrict__ gw, const float* __restrict__ gb,
                 const float* __restrict__ w, const float* __restrict__ bias) {
    __shared__ float sm[CROWS * HH];

    int b    = blockIdx.x;
    int t0   = blockIdx.y * CTILE;
    int tid  = threadIdx.x;
    int warp = tid >> 5;
    int lane = tid & 31;

    for (int rr = warp; rr < CROWS; rr += 8) {
        int l = t0 - CHALO + rr;
        if (l < 0 || l >= LL) {
            #pragma unroll
            for (int j = 0; j < 4; j++)
                *(float4*)&sm[rr * HH + lane * 4 + j * 128] = make_float4(0.f, 0.f, 0.f, 0.f);
            continue;
        }
        const float4* p = (const float4*)(in + ((size_t)(b * LL + l)) * HH);
        float4 v[4];
        #pragma unroll
        for (int j = 0; j < 4; j++) {
            v[j] = p[lane + j * 32];
            if (ADDPE) {
                int c = lane * 4 + j * 128;
                #pragma unroll
                for (int e = 0; e < 4; e++) {
                    int ch = c + e;
                    float freq = expf(-(float)(ch & ~1) * (9.210340371976184f / (float)HH));
                    float a = (float)l * freq;
                    float pe = (ch & 1) ? cosf(a) : sinf(a);
                    (&v[j].x)[e] += pe;
                }
            }
        }
        // write residual stream for core rows only
        if (ADDPE && rr >= CHALO && rr < CHALO + CTILE) {
            float4* rp = (float4*)(resid + ((size_t)(b * LL + l)) * HH);
            #pragma unroll
            for (int j = 0; j < 4; j++) rp[lane + j * 32] = v[j];
        }

        float s = 0.0f;
        #pragma unroll
        for (int j = 0; j < 4; j++) s += v[j].x + v[j].y + v[j].z + v[j].w;
        #pragma unroll
        for (int o = 16; o > 0; o >>= 1) s += __shfl_xor_sync(0xffffffffu, s, o);
        float mean = s * (1.0f / HH);

        float q = 0.0f;
        #pragma unroll
        for (int j = 0; j < 4; j++) {
            float dx = v[j].x - mean, dy = v[j].y - mean;
            float dz = v[j].z - mean, dw = v[j].w - mean;
            q += dx * dx + dy * dy + dz * dz + dw * dw;
        }
        #pragma unroll
        for (int o = 16; o > 0; o >>= 1) q += __shfl_xor_sync(0xffffffffu, q, o);
        float rstd = rsqrtf(q * (1.0f / HH) + 1e-5f);

        #pragma unroll
        for (int j = 0; j < 4; j++) {
            int c = lane * 4 + j * 128;
            float4 g4 = *(const float4*)&gw[c];
            float4 b4 = *(const float4*)&gb[c];
            float4 o4;
            o4.x = (v[j].x - mean) * rstd * g4.x + b4.x;
            o4.y = (v[j].y - mean) * rstd * g4.y + b4.y;
            o4.z = (v[j].z - mean) * rstd * g4.z + b4.z;
            o4.w = (v[j].w - mean) * rstd * g4.w + b4.w;
            *(float4*)&sm[rr * HH + c] = o4;
        }
    }
    __syncthreads();

    int c0 = tid * 2;
    float wr0[KW], wr1[KW];
    #pragma unroll
    for (int k = 0; k < KW; k++) {
        wr0[k] = w[c0 * KW + k];
        wr1[k] = w[(c0 + 1) * KW + k];
    }
    float bi0 = bias[c0], bi1 = bias[c0 + 1];

    #pragma unroll 4
    for (int r = 0; r < CTILE; r++) {
        float a0 = bi0, a1 = bi1;
        #pragma unroll
        for (int k = 0; k < KW; k++) {
            float2 x = *(const float2*)&sm[(r + k) * HH + c0];
            a0 += x.x * wr0[k];
            a1 += x.y * wr1[k];
        }
        *(__half2*)&dwout[((size_t)(b * LL + t0 + r)) * HH + c0] =
            __floats2half2_rn(a0, a1);
    }
}

// ---------------------------------------------------------------------------
// fp16 tensor-core GEMM (R12 config: BM=128, BN=128, BK=32 halves, 3-stage).
// ---------------------------------------------------------------------------
#define GH_ROWW  20
#define GH_SS    (128 * GH_ROWW)
#define GH_NSTG  3
#define GEMM_SMEM (GH_NSTG * GH_SS * 2 * 4)         // 61440 bytes

template <bool RELU, bool RES, typename TOUT>
__global__ void __launch_bounds__(256, 2)
gemm_f16_kernel(const __half* __restrict__ A, const __half* __restrict__ W,
                const float* __restrict__ bias, const float* __restrict__ R,
                TOUT* __restrict__ C, int Md, int Nd, int Kd) {
    extern __shared__ unsigned gsm[];
    unsigned* Asm = gsm;
    unsigned* Bsm = gsm + GH_NSTG * GH_SS;

    int tid  = threadIdx.x;
    int m0   = blockIdx.y * 128;
    int n0   = blockIdx.x * 128;
    int warp = tid >> 5;
    int lane = tid & 31;
    int wm   = (warp >> 2) * 64;
    int wn   = (warp & 3) * 32;
    int lg   = lane >> 2;
    int lq   = lane & 3;

    int lrow = tid >> 2;
    int lchunk = (tid & 3);
    int sw = lrow * GH_ROWW + lchunk * 4;
    int sw2 = (64 + lrow) * GH_ROWW + lchunk * 4;

    const __half* Ag0 = &A[(size_t)(m0 + lrow)      * Kd + lchunk * 8];
    const __half* Ag1 = &A[(size_t)(m0 + 64 + lrow) * Kd + lchunk * 8];
    const __half* Wg0 = &W[(size_t)(n0 + lrow)      * Kd + lchunk * 8];
    const __half* Wg1 = &W[(size_t)(n0 + 64 + lrow) * Kd + lchunk * 8];

    float acc[4][4][4];
    #pragma unroll
    for (int i = 0; i < 4; i++)
        #pragma unroll
        for (int j = 0; j < 4; j++)
            #pragma unroll
            for (int r = 0; r < 4; r++) acc[i][j][r] = 0.0f;

    #define LOAD_STAGE(s, ko)                                                   \
    {                                                                           \
        unsigned* As_ = Asm + (s) * GH_SS;                                      \
        unsigned* Bs_ = Bsm + (s) * GH_SS;                                      \
        cp_async16(As_ + sw,  Ag0 + (ko));                                      \
        cp_async16(As_ + sw2, Ag1 + (ko));                                      \
        cp_async16(Bs_ + sw,  Wg0 + (ko));                                      \
        cp_async16(Bs_ + sw2, Wg1 + (ko));                                      \
        asm volatile("cp.async.commit_group;\n");                               \
    }

    int nit = Kd >> 5;
    LOAD_STAGE(0, 0);
    if (nit > 1) LOAD_STAGE(1, 32);

    for (int it = 0; it < nit; it++) {
        if (it + 1 < nit)
            asm volatile("cp.async.wait_group 1;\n");
        else
            asm volatile("cp.async.wait_group 0;\n");
        __syncthreads();
        if (it + 2 < nit) LOAD_STAGE((it + 2) % GH_NSTG, (it + 2) << 5);

        int cur = it % GH_NSTG;
        const unsigned* Asc = Asm + cur * GH_SS;
        const unsigned* Bsc = Bsm + cur * GH_SS;

        #pragma unroll
        for (int ks = 0; ks < 2; ks++) {
            int kb = ks * 8;
            unsigned af[4][4], bf[4][2];
            #pragma unroll
            for (int mt = 0; mt < 4; mt++) {
                int mr = wm + mt * 16 + lg;
                af[mt][0] = Asc[mr * GH_ROWW + kb + lq];
                af[mt][1] = Asc[(mr + 8) * GH_ROWW + kb + lq];
                af[mt][2] = Asc[mr * GH_ROWW + kb + lq + 4];
                af[mt][3] = Asc[(mr + 8) * GH_ROWW + kb + lq + 4];
            }
            #pragma unroll
            for (int nt = 0; nt < 4; nt++) {
                int nr = wn + nt * 8 + lg;
                bf[nt][0] = Bsc[nr * GH_ROWW + kb + lq];
                bf[nt][1] = Bsc[nr * GH_ROWW + kb + lq + 4];
            }
            #pragma unroll
            for (int mt = 0; mt < 4; mt++)
                #pragma unroll
                for (int nt = 0; nt < 4; nt++)
                    mma_f16(acc[mt][nt], af[mt], bf[nt]);
        }
    }
    #undef LOAD_STAGE

    #pragma unroll
    for (int mt = 0; mt < 4; mt++) {
        #pragma unroll
        for (int half = 0; half < 2; half++) {
            int m = m0 + wm + mt * 16 + lg + half * 8;
            #pragma unroll
            for (int nt = 0; nt < 4; nt++) {
                int n = n0 + wn + nt * 8 + 2 * lq;
                float v0 = acc[mt][nt][half * 2 + 0] + bias[n];
                float v1 = acc[mt][nt][half * 2 + 1] + bias[n + 1];
                if (RELU) { v0 = fmaxf(v0, 0.0f); v1 = fmaxf(v1, 0.0f); }
                if (RES)  { v0 += R[(size_t)m * Nd + n]; v1 += R[(size_t)m * Nd + n + 1]; }
                store2(&C[(size_t)m * Nd + n], v0, v1);
            }
        }
    }
}

// ---------------------------------------------------------------------------
// Fused flash attention, fp16 MMA (m16n8k16), online softmax. (R12 version)
// ---------------------------------------------------------------------------
#define FW 36

__global__ void __launch_bounds__(128)
flash_kernel(const __half* __restrict__ qkv, const int* __restrict__ mask,
             __half* __restrict__ attout) {
    __shared__ unsigned Qs [64 * FW];
    __shared__ unsigned KPs[64 * FW];
    __shared__ unsigned Vst[64 * FW];
    __shared__ int msk[64];

    int bh = blockIdx.x;
    int b  = bh >> 3;
    int h  = bh & 7;
    int q0 = blockIdx.y * 64;

    int tid  = threadIdx.x;
    int warp = tid >> 5;
    int lane = tid & 31;
    int wr   = warp * 16;
    int lg   = lane >> 2;
    int lq   = lane & 3;

    const __half2 qsc = __float2half2_rn(0.125f);

    for (int i = tid; i < 512; i += 128) {
        int r  = i >> 3;
        int cw = (i & 7) * 4;
        int qr = q0 + r; if (qr > LL - 1) qr = LL - 1;
        uint4 v = *(const uint4*)&qkv[((size_t)(b * LL + qr)) * H3 + h * DHH + cw * 2];
        __half2 h0 = __hmul2(*(__half2*)&v.x, qsc);
        __half2 h1 = __hmul2(*(__half2*)&v.y, qsc);
        __half2 h2 = __hmul2(*(__half2*)&v.z, qsc);
        __half2 h3 = __hmul2(*(__half2*)&v.w, qsc);
        uint4 sv;
        sv.x = *(unsigned*)&h0; sv.y = *(unsigned*)&h1;
        sv.z = *(unsigned*)&h2; sv.w = *(unsigned*)&h3;
        *(uint4*)&Qs[r * FW + cw] = sv;
    }

    float oacc[8][4];
    #pragma unroll
    for (int nt = 0; nt < 8; nt++)
        #pragma unroll
        for (int r2 = 0; r2 < 4; r2++) oacc[nt][r2] = 0.0f;
    float m0 = -1e30f, m1 = -1e30f, l0 = 0.0f, l1 = 0.0f;

    for (int kt = 0; kt < LL; kt += 64) {
        __syncthreads();

        for (int i = tid; i < 512; i += 128) {
            int r  = i >> 3;
            int cw = (i & 7) * 4;
            int kr = kt + r; if (kr > LL - 1) kr = LL - 1;
            const __half* base = &qkv[((size_t)(b * LL + kr)) * H3 + h * DHH + cw * 2];
            uint4 kv = *(const uint4*)(base + HH);
            *(uint4*)&KPs[r * FW + cw] = kv;
            uint4 vv = *(const uint4*)(base + 2 * HH);
            const __half* vh = (const __half*)&vv;
            __half* Vh = (__half*)Vst;
            #pragma unroll
            for (int j = 0; j < 8; j++)
                Vh[(cw * 2 + j) * (FW * 2) + r] = vh[j];
        }
        if (tid < 64) msk[tid] = (kt + tid < LL) ? mask[b * LL + kt + tid] : 0;
        __syncthreads();

        float sacc[8][4];
        #pragma unroll
        for (int nt = 0; nt < 8; nt++)
            #pragma unroll
            for (int r2 = 0; r2 < 4; r2++) sacc[nt][r2] = 0.0f;

        #pragma unroll
        for (int ks = 0; ks < 4; ks++) {
            int kb = ks * 8;
            unsigned af[4];
            af[0] = Qs[(wr + lg)     * FW + kb + lq];
            af[1] = Qs[(wr + lg + 8) * FW + kb + lq];
            af[2] = Qs[(wr + lg)     * FW + kb + lq + 4];
            af[3] = Qs[(wr + lg + 8) * FW + kb + lq + 4];
            #pragma unroll
            for (int nt = 0; nt < 8; nt++) {
                unsigned bf[2];
                bf[0] = KPs[(nt * 8 + lg) * FW + kb + lq];
                bf[1] = KPs[(nt * 8 + lg) * FW + kb + lq + 4];
                mma_f16(sacc[nt], af, bf);
            }
        }

        float rmax0 = -1e30f, rmax1 = -1e30f;
        #pragma unroll
        for (int nt = 0; nt < 8; nt++) {
            #pragma unroll
            for (int j = 0; j < 2; j++) {
                int kl = nt * 8 + 2 * lq + j;
                bool ok = (kt + kl < LL) && (msk[kl] > 0);
                if (!ok) { sacc[nt][j] = -1e30f; sacc[nt][2 + j] = -1e30f; }
                rmax0 = fmaxf(rmax0, sacc[nt][j]);
                rmax1 = fmaxf(rmax1, sacc[nt][2 + j]);
            }
        }
        #pragma unroll
        for (int o = 1; o <= 2; o <<= 1) {
            rmax0 = fmaxf(rmax0, __shfl_xor_sync(0xffffffffu, rmax0, o));
            rmax1 = fmaxf(rmax1, __shfl_xor_sync(0xffffffffu, rmax1, o));
        }

        float m0n = fmaxf(m0, rmax0);
        float m1n = fmaxf(m1, rmax1);
        float alpha0 = __expf(m0 - m0n);
        float alpha1 = __expf(m1 - m1n);
        m0 = m0n; m1 = m1n;

        float rs0 = 0.0f, rs1 = 0.0f;
        #pragma unroll
        for (int nt = 0; nt < 8; nt++) {
            #pragma unroll
            for (int j = 0; j < 2; j++) {
                float p0 = __expf(sacc[nt][j] - m0);
                float p1 = __expf(sacc[nt][2 + j] - m1);
                sacc[nt][j] = p0;     rs0 += p0;
                sacc[nt][2 + j] = p1; rs1 += p1;
            }
        }
        #pragma unroll
        for (int o = 1; o <= 2; o <<= 1) {
            rs0 += __shfl_xor_sync(0xffffffffu, rs0, o);
            rs1 += __shfl_xor_sync(0xffffffffu, rs1, o);
        }
        l0 = l0 * alpha0 + rs0;
        l1 = l1 * alpha1 + rs1;

        #pragma unroll
        for (int nt = 0; nt < 8; nt++) {
            oacc[nt][0] *= alpha0; oacc[nt][1] *= alpha0;
            oacc[nt][2] *= alpha1; oacc[nt][3] *= alpha1;
        }

        __syncthreads();

        #pragma unroll
        for (int nt = 0; nt < 8; nt++) {
            __half2 p01 = __floats2half2_rn(sacc[nt][0], sacc[nt][1]);
            __half2 p23 = __floats2half2_rn(sacc[nt][2], sacc[nt][3]);
            KPs[(wr + lg)     * FW + nt * 4 + lq] = *(unsigned*)&p01;
            KPs[(wr + lg + 8) * FW + nt * 4 + lq] = *(unsigned*)&p23;
        }
        __syncwarp();

        #pragma unroll
        for (int ks = 0; ks < 4; ks++) {
            int kb = ks * 8;
            unsigned af[4];
            af[0] = KPs[(wr + lg)     * FW + kb + lq];
            af[1] = KPs[(wr + lg + 8) * FW + kb + lq];
            af[2] = KPs[(wr + lg)     * FW + kb + lq + 4];
            af[3] = KPs[(wr + lg + 8) * FW + kb + lq + 4];
            #pragma unroll
            for (int nt = 0; nt < 8; nt++) {
                unsigned bf[2];
                bf[0] = Vst[(nt * 8 + lg) * FW + kb + lq];
                bf[1] = Vst[(nt * 8 + lg) * FW + kb + lq + 4];
                mma_f16(oacc[nt], af, bf);
            }
        }
    }

    float inv0 = 1.0f / fmaxf(l0, 1e-30f);
    float inv1 = 1.0f / fmaxf(l1, 1e-30f);
    int r0 = q0 + wr + lg;
    int r1 = r0 + 8;
    #pragma unroll
    for (int nt = 0; nt < 8; nt++) {
        int c = nt * 8 + 2 * lq;
        if (r0 < LL)
            *(__half2*)&attout[((size_t)(b * LL + r0)) * HH + h * DHH + c] =
                __floats2half2_rn(oacc[nt][0] * inv0, oacc[nt][1] * inv0);
        if (r1 < LL)
            *(__half2*)&attout[((size_t)(b * LL + r1)) * HH + h * DHH + c] =
                __floats2half2_rn(oacc[nt][2] * inv1, oacc[nt][3] * inv1);
    }
}

// ---------------------------------------------------------------------------
// Launch
// ---------------------------------------------------------------------------
extern "C" void kernel_launch(void* const* d_in, const int* in_sizes, int n_in,
                              void* d_out, int out_size) {
    const float* x         = (const float*)d_in[0];
    const int*   mask      = (const int*)  d_in[1];
    const float* conv_ln_g = (const float*)d_in[2];
    const float* conv_ln_b = (const float*)d_in[3];
    const float* dw_w      = (const float*)d_in[4];
    const float* dw_b      = (const float*)d_in[5];
    const float* pw_w      = (const float*)d_in[6];
    const float* pw_b      = (const float*)d_in[7];
    const float* att_ln_g  = (const float*)d_in[8];
    const float* att_ln_b  = (const float*)d_in[9];
    const float* qkv_w     = (const float*)d_in[10];
    const float* qkv_b     = (const float*)d_in[11];
    const float* out_w     = (const float*)d_in[12];
    const float* out_b     = (const float*)d_in[13];
    const float* ff_ln_g   = (const float*)d_in[14];
    const float* ff_ln_b   = (const float*)d_in[15];
    const float* ff_w      = (const float*)d_in[16];
    const float* ff_b      = (const float*)d_in[17];
    float* out = (float*)d_out;

    __half *normh, *dwouth, *qkvh, *attouth, *wth;
    cudaGetSymbolAddress((void**)&normh,   g_norm_h);
    cudaGetSymbolAddress((void**)&dwouth,  g_dwout_h);
    cudaGetSymbolAddress((void**)&qkvh,    g_qkv_h);
    cudaGetSymbolAddress((void**)&attouth, g_attout_h);
    cudaGetSymbolAddress((void**)&wth,     g_wth);

    cudaFuncSetAttribute(gemm_f16_kernel<true, true, float>,
                         cudaFuncAttributeMaxDynamicSharedMemorySize, GEMM_SMEM);
    cudaFuncSetAttribute(gemm_f16_kernel<false, false, __half>,
                         cudaFuncAttributeMaxDynamicSharedMemorySize, GEMM_SMEM);
    cudaFuncSetAttribute(gemm_f16_kernel<false, true, float>,
                         cudaFuncAttributeMaxDynamicSharedMemorySize, GEMM_SMEM);

    conv_all_w_kernel<<<(WT_TOT / 4 + 255) / 256, 256>>>(pw_w, qkv_w, out_w, ff_w, wth);

    // Conv block 0: fused (x + pe) -> resid(out) + LN + dwconv
    ln_dwconv_kernel<true><<<dim3(BB, LL / CTILE), 256>>>(
        x, out, dwouth, conv_ln_g, conv_ln_b, dw_w, dw_b);
    gemm_f16_kernel<true, true, float><<<dim3(HH / 128, MM / 128), 256, GEMM_SMEM>>>(
        dwouth, wth + WT_PW, pw_b, out, out, MM, HH, HH);

    // Conv blocks 1..3
    for (int i = 1; i < NCC; i++) {
        ln_dwconv_kernel<false><<<dim3(BB, LL / CTILE), 256>>>(
            out, nullptr, dwouth, conv_ln_g + i * HH, conv_ln_b + i * HH,
            dw_w + i * HH * KW, dw_b + i * HH);
        gemm_f16_kernel<true, true, float><<<dim3(HH / 128, MM / 128), 256, GEMM_SMEM>>>(
            dwouth, wth + WT_PW + (size_t)i * HH * HH, pw_b + i * HH, out, out, MM, HH, HH);
    }

    ln_h_kernel<<<MM, 128>>>(out, normh, att_ln_g, att_ln_b);
    gemm_f16_kernel<false, false, __half><<<dim3(H3 / 128, MM / 128), 256, GEMM_SMEM>>>(
        normh, wth + WT_QKV, qkv_b, (const float*)nullptr, qkvh, MM, H3, HH);

    flash_kernel<<<dim3(BB * NHH, (LL + 63) / 64), 128>>>(qkvh, mask, attouth);

    gemm_f16_kernel<false, true, float><<<dim3(HH / 128, MM / 128), 256, GEMM_SMEM>>>(
        attouth, wth + WT_OUT, out_b, out, out, MM, HH, HH);

    ln_h_kernel<<<MM, 128>>>(out, normh, ff_ln_g, ff_ln_b);
    gemm_f16_kernel<true, true, float><<<dim3(HH / 128, MM / 128), 256, GEMM_SMEM>>>(
        normh, wth + WT_FF, ff_b, out, out, MM, HH, HH);
}

// round 15
// speedup vs baseline: 1.1274x; 1.0451x over previous
#include <cuda_runtime.h>
#include <cuda_fp16.h>
#include <math.h>
#include <stdint.h>

// Problem constants
#define BB   32
#define LL   400
#define HH   512
#define NHH  8
#define DHH  64
#define KW   7
#define NCC  4
#define MM   (BB * LL)      // 12800 tokens
#define H3   (3 * HH)       // 1536

// ---------------------------------------------------------------------------
// Scratch
// ---------------------------------------------------------------------------
__device__ __half g_norm_h [MM * HH];
__device__ __half g_dwout_h[MM * HH];
__device__ __half g_qkv_h  [MM * H3];
__device__ __half g_attout_h[MM * HH];
// fp16 weights: pw | qkv | out | ff
#define WT_PW   0
#define WT_QKV  (NCC * HH * HH)
#define WT_OUT  (WT_QKV + H3 * HH)
#define WT_FF   (WT_OUT + HH * HH)
#define WT_TOT  (WT_FF + HH * HH)
__device__ __half g_wth[WT_TOT];

// ---------------------------------------------------------------------------
// helpers
// ---------------------------------------------------------------------------
__device__ __forceinline__ void mma_f16(float* d, const unsigned* a, const unsigned* b) {
    asm volatile(
        "mma.sync.aligned.m16n8k16.row.col.f32.f16.f16.f32 "
        "{%0,%1,%2,%3}, {%4,%5,%6,%7}, {%8,%9}, {%0,%1,%2,%3};\n"
        : "+f"(d[0]), "+f"(d[1]), "+f"(d[2]), "+f"(d[3])
        : "r"(a[0]), "r"(a[1]), "r"(a[2]), "r"(a[3]), "r"(b[0]), "r"(b[1]));
}

__device__ __forceinline__ void ldsm_x4(unsigned* r, unsigned addr) {
    asm volatile("ldmatrix.sync.aligned.m8n8.x4.shared.b16 {%0,%1,%2,%3}, [%4];"
                 : "=r"(r[0]), "=r"(r[1]), "=r"(r[2]), "=r"(r[3]) : "r"(addr));
}
__device__ __forceinline__ void ldsm_x2(unsigned* r, unsigned addr) {
    asm volatile("ldmatrix.sync.aligned.m8n8.x2.shared.b16 {%0,%1}, [%2];"
                 : "=r"(r[0]), "=r"(r[1]) : "r"(addr));
}

__device__ __forceinline__ void cp_async16(void* smem_dst, const void* gsrc) {
    unsigned sa = (unsigned)__cvta_generic_to_shared(smem_dst);
    asm volatile("cp.async.cg.shared.global [%0], [%1], 16;\n" :: "r"(sa), "l"(gsrc));
}

__device__ __forceinline__ void store2(float* p, float a, float b) {
    *(float2*)p = make_float2(a, b);
}
__device__ __forceinline__ void store2(__half* p, float a, float b) {
    *(__half2*)p = __floats2half2_rn(a, b);
}

// ---------------------------------------------------------------------------
// Weight pre-convert to fp16 (one launch).
// ---------------------------------------------------------------------------
__global__ void conv_all_w_kernel(const float* __restrict__ pw,
                                  const float* __restrict__ qkvw,
                                  const float* __restrict__ ow,
                                  const float* __restrict__ ffw,
                                  __half* __restrict__ out) {
    int i = blockIdx.x * blockDim.x + threadIdx.x;
    const int n_pw  = WT_QKV / 4;
    const int n_qkv = (WT_OUT - WT_QKV) / 4;
    const int n_o   = (WT_FF - WT_OUT) / 4;
    const int n_tot = WT_TOT / 4;
    if (i >= n_tot) return;
    const float* src; int off;
    if (i < n_pw)                     { src = pw;   off = i; }
    else if (i < n_pw + n_qkv)        { src = qkvw; off = i - n_pw; }
    else if (i < n_pw + n_qkv + n_o)  { src = ow;   off = i - n_pw - n_qkv; }
    else                              { src = ffw;  off = i - n_pw - n_qkv - n_o; }
    float4 v = ((const float4*)src)[off];
    ((__half2*)out)[i * 2]     = __floats2half2_rn(v.x, v.y);
    ((__half2*)out)[i * 2 + 1] = __floats2half2_rn(v.z, v.w);
}

// ---------------------------------------------------------------------------
// LayerNorm -> fp16 output. One block/row, 128 thr.
// ---------------------------------------------------------------------------
__global__ void ln_h_kernel(const float* __restrict__ in, __half* __restrict__ out,
                            const float* __restrict__ gw, const float* __restrict__ gb) {
    int row = blockIdx.x;
    int t   = threadIdx.x;  // 128
    const float4* p = (const float4*)(in + (size_t)row * HH);
    float4 v = p[t];

    __shared__ float sh[4];

    float s = v.x + v.y + v.z + v.w;
    #pragma unroll
    for (int o = 16; o > 0; o >>= 1) s += __shfl_down_sync(0xffffffffu, s, o);
    if ((t & 31) == 0) sh[t >> 5] = s;
    __syncthreads();
    float mean = (sh[0] + sh[1] + sh[2] + sh[3]) * (1.0f / HH);
    __syncthreads();

    float dx = v.x - mean, dy = v.y - mean, dz = v.z - mean, dw = v.w - mean;
    float q = dx * dx + dy * dy + dz * dz + dw * dw;
    #pragma unroll
    for (int o = 16; o > 0; o >>= 1) q += __shfl_down_sync(0xffffffffu, q, o);
    if ((t & 31) == 0) sh[t >> 5] = q;
    __syncthreads();
    float var  = (sh[0] + sh[1] + sh[2] + sh[3]) * (1.0f / HH);
    float rstd = rsqrtf(var + 1e-5f);

    float4 g4 = ((const float4*)gw)[t];
    float4 b4 = ((const float4*)gb)[t];
    float ox = dx * rstd * g4.x + b4.x;
    float oy = dy * rstd * g4.y + b4.y;
    float oz = dz * rstd * g4.z + b4.z;
    float ow = dw * rstd * g4.w + b4.w;
    __half2* o2 = (__half2*)(out + (size_t)row * HH);
    o2[t * 2]     = __floats2half2_rn(ox, oy);
    o2[t * 2 + 1] = __floats2half2_rn(oz, ow);
}

// ---------------------------------------------------------------------------
// Fused (optional PE-add) + LayerNorm + depthwise conv (K=7, pad 3).
// ---------------------------------------------------------------------------
#define CTILE 16
#define CHALO 3
#define CROWS (CTILE + 2 * CHALO)   // 22

template <bool ADDPE>
__global__ void __launch_bounds__(256)
ln_dwconv_kernel(const float* __restrict__ in, float* __restrict__ resid,
                 __half* __restrict__ dwout,
                 const float* __restrict__ gw, const float* __restrict__ gb,
                 const float* __restrict__ w, const float* __restrict__ bias) {
    __shared__ float sm[CROWS * HH];

    int b    = blockIdx.x;
    int t0   = blockIdx.y * CTILE;
    int tid  = threadIdx.x;
    int warp = tid >> 5;
    int lane = tid & 31;

    for (int rr = warp; rr < CROWS; rr += 8) {
        int l = t0 - CHALO + rr;
        if (l < 0 || l >= LL) {
            #pragma unroll
            for (int j = 0; j < 4; j++)
                *(float4*)&sm[rr * HH + lane * 4 + j * 128] = make_float4(0.f, 0.f, 0.f, 0.f);
            continue;
        }
        const float4* p = (const float4*)(in + ((size_t)(b * LL + l)) * HH);
        float4 v[4];
        #pragma unroll
        for (int j = 0; j < 4; j++) {
            v[j] = p[lane + j * 32];
            if (ADDPE) {
                int c = lane * 4 + j * 128;
                #pragma unroll
                for (int e = 0; e < 4; e++) {
                    int ch = c + e;
                    float freq = expf(-(float)(ch & ~1) * (9.210340371976184f / (float)HH));
                    float a = (float)l * freq;
                    float pe = (ch & 1) ? cosf(a) : sinf(a);
                    (&v[j].x)[e] += pe;
                }
            }
        }
        if (ADDPE && rr >= CHALO && rr < CHALO + CTILE) {
            float4* rp = (float4*)(resid + ((size_t)(b * LL + l)) * HH);
            #pragma unroll
            for (int j = 0; j < 4; j++) rp[lane + j * 32] = v[j];
        }

        float s = 0.0f;
        #pragma unroll
        for (int j = 0; j < 4; j++) s += v[j].x + v[j].y + v[j].z + v[j].w;
        #pragma unroll
        for (int o = 16; o > 0; o >>= 1) s += __shfl_xor_sync(0xffffffffu, s, o);
        float mean = s * (1.0f / HH);

        float q = 0.0f;
        #pragma unroll
        for (int j = 0; j < 4; j++) {
            float dx = v[j].x - mean, dy = v[j].y - mean;
            float dz = v[j].z - mean, dw = v[j].w - mean;
            q += dx * dx + dy * dy + dz * dz + dw * dw;
        }
        #pragma unroll
        for (int o = 16; o > 0; o >>= 1) q += __shfl_xor_sync(0xffffffffu, q, o);
        float rstd = rsqrtf(q * (1.0f / HH) + 1e-5f);

        #pragma unroll
        for (int j = 0; j < 4; j++) {
            int c = lane * 4 + j * 128;
            float4 g4 = *(const float4*)&gw[c];
            float4 b4 = *(const float4*)&gb[c];
            float4 o4;
            o4.x = (v[j].x - mean) * rstd * g4.x + b4.x;
            o4.y = (v[j].y - mean) * rstd * g4.y + b4.y;
            o4.z = (v[j].z - mean) * rstd * g4.z + b4.z;
            o4.w = (v[j].w - mean) * rstd * g4.w + b4.w;
            *(float4*)&sm[rr * HH + c] = o4;
        }
    }
    __syncthreads();

    int c0 = tid * 2;
    float wr0[KW], wr1[KW];
    #pragma unroll
    for (int k = 0; k < KW; k++) {
        wr0[k] = w[c0 * KW + k];
        wr1[k] = w[(c0 + 1) * KW + k];
    }
    float bi0 = bias[c0], bi1 = bias[c0 + 1];

    #pragma unroll 4
    for (int r = 0; r < CTILE; r++) {
        float a0 = bi0, a1 = bi1;
        #pragma unroll
        for (int k = 0; k < KW; k++) {
            float2 x = *(const float2*)&sm[(r + k) * HH + c0];
            a0 += x.x * wr0[k];
            a1 += x.y * wr1[k];
        }
        *(__half2*)&dwout[((size_t)(b * LL + t0 + r)) * HH + c0] =
            __floats2half2_rn(a0, a1);
    }
}

// ---------------------------------------------------------------------------
// fp16 tensor-core GEMM: BM=128, BN=128, BK=32 halves, 3-stage cp.async,
// ldmatrix fragment loads (A: x4, B: x2), pad stride 20 words.
// ---------------------------------------------------------------------------
#define GH_ROWW  20
#define GH_SS    (128 * GH_ROWW)
#define GH_NSTG  3
#define GEMM_SMEM (GH_NSTG * GH_SS * 2 * 4)         // 61440 bytes

template <bool RELU, bool RES, typename TOUT>
__global__ void __launch_bounds__(256, 2)
gemm_f16_kernel(const __half* __restrict__ A, const __half* __restrict__ W,
                const float* __restrict__ bias, const float* __restrict__ R,
                TOUT* __restrict__ C, int Md, int Nd, int Kd) {
    extern __shared__ unsigned gsm[];
    unsigned* Asm = gsm;
    unsigned* Bsm = gsm + GH_NSTG * GH_SS;

    int tid  = threadIdx.x;
    int m0   = blockIdx.y * 128;
    int n0   = blockIdx.x * 128;
    int warp = tid >> 5;
    int lane = tid & 31;
    int wm   = (warp >> 2) * 64;
    int wn   = (warp & 3) * 32;
    int lg   = lane >> 2;
    int lq   = lane & 3;

    int lrow = tid >> 2;
    int lchunk = (tid & 3);
    int sw = lrow * GH_ROWW + lchunk * 4;
    int sw2 = (64 + lrow) * GH_ROWW + lchunk * 4;

    // ldmatrix per-lane word offsets (stage-relative)
    int aOff[4], bOff[4];
    #pragma unroll
    for (int mt = 0; mt < 4; mt++)
        aOff[mt] = (wm + mt * 16 + (lane & 15)) * GH_ROWW + ((lane >> 4) * 4);
    #pragma unroll
    for (int nt = 0; nt < 4; nt++)
        bOff[nt] = (wn + nt * 8 + (lane & 7)) * GH_ROWW + (((lane >> 3) & 1) * 4);

    const __half* Ag0 = &A[(size_t)(m0 + lrow)      * Kd + lchunk * 8];
    const __half* Ag1 = &A[(size_t)(m0 + 64 + lrow) * Kd + lchunk * 8];
    const __half* Wg0 = &W[(size_t)(n0 + lrow)      * Kd + lchunk * 8];
    const __half* Wg1 = &W[(size_t)(n0 + 64 + lrow) * Kd + lchunk * 8];

    float acc[4][4][4];
    #pragma unroll
    for (int i = 0; i < 4; i++)
        #pragma unroll
        for (int j = 0; j < 4; j++)
            #pragma unroll
            for (int r = 0; r < 4; r++) acc[i][j][r] = 0.0f;

    #define LOAD_STAGE(s, ko)                                                   \
    {                                                                           \
        unsigned* As_ = Asm + (s) * GH_SS;                                      \
        unsigned* Bs_ = Bsm + (s) * GH_SS;                                      \
        cp_async16(As_ + sw,  Ag0 + (ko));                                      \
        cp_async16(As_ + sw2, Ag1 + (ko));                                      \
        cp_async16(Bs_ + sw,  Wg0 + (ko));                                      \
        cp_async16(Bs_ + sw2, Wg1 + (ko));                                      \
        asm volatile("cp.async.commit_group;\n");                               \
    }

    int nit = Kd >> 5;
    LOAD_STAGE(0, 0);
    if (nit > 1) LOAD_STAGE(1, 32);

    for (int it = 0; it < nit; it++) {
        if (it + 1 < nit)
            asm volatile("cp.async.wait_group 1;\n");
        else
            asm volatile("cp.async.wait_group 0;\n");
        __syncthreads();
        if (it + 2 < nit) LOAD_STAGE((it + 2) % GH_NSTG, (it + 2) << 5);

        int cur = it % GH_NSTG;
        unsigned aBase = (unsigned)__cvta_generic_to_shared(Asm + cur * GH_SS);
        unsigned bBase = (unsigned)__cvta_generic_to_shared(Bsm + cur * GH_SS);

        #pragma unroll
        for (int ks = 0; ks < 2; ks++) {
            int kb = ks * 8;
            unsigned af[4][4], bf[4][2];
            #pragma unroll
            for (int mt = 0; mt < 4; mt++)
                ldsm_x4(af[mt], aBase + (unsigned)(aOff[mt] + kb) * 4u);
            #pragma unroll
            for (int nt = 0; nt < 4; nt++)
                ldsm_x2(bf[nt], bBase + (unsigned)(bOff[nt] + kb) * 4u);
            #pragma unroll
            for (int mt = 0; mt < 4; mt++)
                #pragma unroll
                for (int nt = 0; nt < 4; nt++)
                    mma_f16(acc[mt][nt], af[mt], bf[nt]);
        }
    }
    #undef LOAD_STAGE

    #pragma unroll
    for (int mt = 0; mt < 4; mt++) {
        #pragma unroll
        for (int half = 0; half < 2; half++) {
            int m = m0 + wm + mt * 16 + lg + half * 8;
            #pragma unroll
            for (int nt = 0; nt < 4; nt++) {
                int n = n0 + wn + nt * 8 + 2 * lq;
                float v0 = acc[mt][nt][half * 2 + 0] + bias[n];
                float v1 = acc[mt][nt][half * 2 + 1] + bias[n + 1];
                if (RELU) { v0 = fmaxf(v0, 0.0f); v1 = fmaxf(v1, 0.0f); }
                if (RES)  { v0 += R[(size_t)m * Nd + n]; v1 += R[(size_t)m * Nd + n + 1]; }
                store2(&C[(size_t)m * Nd + n], v0, v1);
            }
        }
    }
}

// ---------------------------------------------------------------------------
// Fused flash attention, fp16 MMA (m16n8k16), online softmax.
// ---------------------------------------------------------------------------
#define FW 36

__global__ void __launch_bounds__(128)
flash_kernel(const __half* __restrict__ qkv, const int* __restrict__ mask,
             __half* __restrict__ attout) {
    __shared__ unsigned Qs [64 * FW];
    __shared__ unsigned KPs[64 * FW];
    __shared__ unsigned Vst[64 * FW];
    __shared__ int msk[64];

    int bh = blockIdx.x;
    int b  = bh >> 3;
    int h  = bh & 7;
    int q0 = blockIdx.y * 64;

    int tid  = threadIdx.x;
    int warp = tid >> 5;
    int lane = tid & 31;
    int wr   = warp * 16;
    int lg   = lane >> 2;
    int lq   = lane & 3;

    const __half2 qsc = __float2half2_rn(0.125f);

    for (int i = tid; i < 512; i += 128) {
        int r  = i >> 3;
        int cw = (i & 7) * 4;
        int qr = q0 + r; if (qr > LL - 1) qr = LL - 1;
        uint4 v = *(const uint4*)&qkv[((size_t)(b * LL + qr)) * H3 + h * DHH + cw * 2];
        __half2 h0 = __hmul2(*(__half2*)&v.x, qsc);
        __half2 h1 = __hmul2(*(__half2*)&v.y, qsc);
        __half2 h2 = __hmul2(*(__half2*)&v.z, qsc);
        __half2 h3 = __hmul2(*(__half2*)&v.w, qsc);
        uint4 sv;
        sv.x = *(unsigned*)&h0; sv.y = *(unsigned*)&h1;
        sv.z = *(unsigned*)&h2; sv.w = *(unsigned*)&h3;
        *(uint4*)&Qs[r * FW + cw] = sv;
    }

    float oacc[8][4];
    #pragma unroll
    for (int nt = 0; nt < 8; nt++)
        #pragma unroll
        for (int r2 = 0; r2 < 4; r2++) oacc[nt][r2] = 0.0f;
    float m0 = -1e30f, m1 = -1e30f, l0 = 0.0f, l1 = 0.0f;

    for (int kt = 0; kt < LL; kt += 64) {
        __syncthreads();

        for (int i = tid; i < 512; i += 128) {
            int r  = i >> 3;
            int cw = (i & 7) * 4;
            int kr = kt + r; if (kr > LL - 1) kr = LL - 1;
            const __half* base = &qkv[((size_t)(b * LL + kr)) * H3 + h * DHH + cw * 2];
            uint4 kv = *(const uint4*)(base + HH);
            *(uint4*)&KPs[r * FW + cw] = kv;
            uint4 vv = *(const uint4*)(base + 2 * HH);
            const __half* vh = (const __half*)&vv;
            __half* Vh = (__half*)Vst;
            #pragma unroll
            for (int j = 0; j < 8; j++)
                Vh[(cw * 2 + j) * (FW * 2) + r] = vh[j];
        }
        if (tid < 64) msk[tid] = (kt + tid < LL) ? mask[b * LL + kt + tid] : 0;
        __syncthreads();

        float sacc[8][4];
        #pragma unroll
        for (int nt = 0; nt < 8; nt++)
            #pragma unroll
            for (int r2 = 0; r2 < 4; r2++) sacc[nt][r2] = 0.0f;

        #pragma unroll
        for (int ks = 0; ks < 4; ks++) {
            int kb = ks * 8;
            unsigned af[4];
            af[0] = Qs[(wr + lg)     * FW + kb + lq];
            af[1] = Qs[(wr + lg + 8) * FW + kb + lq];
            af[2] = Qs[(wr + lg)     * FW + kb + lq + 4];
            af[3] = Qs[(wr + lg + 8) * FW + kb + lq + 4];
            #pragma unroll
            for (int nt = 0; nt < 8; nt++) {
                unsigned bf[2];
                bf[0] = KPs[(nt * 8 + lg) * FW + kb + lq];
                bf[1] = KPs[(nt * 8 + lg) * FW + kb + lq + 4];
                mma_f16(sacc[nt], af, bf);
            }
        }

        float rmax0 = -1e30f, rmax1 = -1e30f;
        #pragma unroll
        for (int nt = 0; nt < 8; nt++) {
            #pragma unroll
            for (int j = 0; j < 2; j++) {
                int kl = nt * 8 + 2 * lq + j;
                bool ok = (kt + kl < LL) && (msk[kl] > 0);
                if (!ok) { sacc[nt][j] = -1e30f; sacc[nt][2 + j] = -1e30f; }
                rmax0 = fmaxf(rmax0, sacc[nt][j]);
                rmax1 = fmaxf(rmax1, sacc[nt][2 + j]);
            }
        }
        #pragma unroll
        for (int o = 1; o <= 2; o <<= 1) {
            rmax0 = fmaxf(rmax0, __shfl_xor_sync(0xffffffffu, rmax0, o));
            rmax1 = fmaxf(rmax1, __shfl_xor_sync(0xffffffffu, rmax1, o));
        }

        float m0n = fmaxf(m0, rmax0);
        float m1n = fmaxf(m1, rmax1);
        float alpha0 = __expf(m0 - m0n);
        float alpha1 = __expf(m1 - m1n);
        m0 = m0n; m1 = m1n;

        float rs0 = 0.0f, rs1 = 0.0f;
        #pragma unroll
        for (int nt = 0; nt < 8; nt++) {
            #pragma unroll
            for (int j = 0; j < 2; j++) {
                float p0 = __expf(sacc[nt][j] - m0);
                float p1 = __expf(sacc[nt][2 + j] - m1);
                sacc[nt][j] = p0;     rs0 += p0;
                sacc[nt][2 + j] = p1; rs1 += p1;
            }
        }
        #pragma unroll
        for (int o = 1; o <= 2; o <<= 1) {
            rs0 += __shfl_xor_sync(0xffffffffu, rs0, o);
            rs1 += __shfl_xor_sync(0xffffffffu, rs1, o);
        }
        l0 = l0 * alpha0 + rs0;
        l1 = l1 * alpha1 + rs1;

        #pragma unroll
        for (int nt = 0; nt < 8; nt++) {
            oacc[nt][0] *= alpha0; oacc[nt][1] *= alpha0;
            oacc[nt][2] *= alpha1; oacc[nt][3] *= alpha1;
        }

        __syncthreads();

        #pragma unroll
        for (int nt = 0; nt < 8; nt++) {
            __half2 p01 = __floats2half2_rn(sacc[nt][0], sacc[nt][1]);
            __half2 p23 = __floats2half2_rn(sacc[nt][2], sacc[nt][3]);
            KPs[(wr + lg)     * FW + nt * 4 + lq] = *(unsigned*)&p01;
            KPs[(wr + lg + 8) * FW + nt * 4 + lq] = *(unsigned*)&p23;
        }
        __syncwarp();

        #pragma unroll
        for (int ks = 0; ks < 4; ks++) {
            int kb = ks * 8;
            unsigned af[4];
            af[0] = KPs[(wr + lg)     * FW + kb + lq];
            af[1] = KPs[(wr + lg + 8) * FW + kb + lq];
            af[2] = KPs[(wr + lg)     * FW + kb + lq + 4];
            af[3] = KPs[(wr + lg + 8) * FW + kb + lq + 4];
            #pragma unroll
            for (int nt = 0; nt < 8; nt++) {
                unsigned bf[2];
                bf[0] = Vst[(nt * 8 + lg) * FW + kb + lq];
                bf[1] = Vst[(nt * 8 + lg) * FW + kb + lq + 4];
                mma_f16(oacc[nt], af, bf);
            }
        }
    }

    float inv0 = 1.0f / fmaxf(l0, 1e-30f);
    float inv1 = 1.0f / fmaxf(l1, 1e-30f);
    int r0 = q0 + wr + lg;
    int r1 = r0 + 8;
    #pragma unroll
    for (int nt = 0; nt < 8; nt++) {
        int c = nt * 8 + 2 * lq;
        if (r0 < LL)
            *(__half2*)&attout[((size_t)(b * LL + r0)) * HH + h * DHH + c] =
                __floats2half2_rn(oacc[nt][0] * inv0, oacc[nt][1] * inv0);
        if (r1 < LL)
            *(__half2*)&attout[((size_t)(b * LL + r1)) * HH + h * DHH + c] =
                __floats2half2_rn(oacc[nt][2] * inv1, oacc[nt][3] * inv1);
    }
}

// ---------------------------------------------------------------------------
// Launch
// ---------------------------------------------------------------------------
extern "C" void kernel_launch(void* const* d_in, const int* in_sizes, int n_in,
                              void* d_out, int out_size) {
    const float* x         = (const float*)d_in[0];
    const int*   mask      = (const int*)  d_in[1];
    const float* conv_ln_g = (const float*)d_in[2];
    const float* conv_ln_b = (const float*)d_in[3];
    const float* dw_w      = (const float*)d_in[4];
    const float* dw_b      = (const float*)d_in[5];
    const float* pw_w      = (const float*)d_in[6];
    const float* pw_b      = (const float*)d_in[7];
    const float* att_ln_g  = (const float*)d_in[8];
    const float* att_ln_b  = (const float*)d_in[9];
    const float* qkv_w     = (const float*)d_in[10];
    const float* qkv_b     = (const float*)d_in[11];
    const float* out_w     = (const float*)d_in[12];
    const float* out_b     = (const float*)d_in[13];
    const float* ff_ln_g   = (const float*)d_in[14];
    const float* ff_ln_b   = (const float*)d_in[15];
    const float* ff_w      = (const float*)d_in[16];
    const float* ff_b      = (const float*)d_in[17];
    float* out = (float*)d_out;

    __half *normh, *dwouth, *qkvh, *attouth, *wth;
    cudaGetSymbolAddress((void**)&normh,   g_norm_h);
    cudaGetSymbolAddress((void**)&dwouth,  g_dwout_h);
    cudaGetSymbolAddress((void**)&qkvh,    g_qkv_h);
    cudaGetSymbolAddress((void**)&attouth, g_attout_h);
    cudaGetSymbolAddress((void**)&wth,     g_wth);

    cudaFuncSetAttribute(gemm_f16_kernel<true, true, float>,
                         cudaFuncAttributeMaxDynamicSharedMemorySize, GEMM_SMEM);
    cudaFuncSetAttribute(gemm_f16_kernel<false, false, __half>,
                         cudaFuncAttributeMaxDynamicSharedMemorySize, GEMM_SMEM);
    cudaFuncSetAttribute(gemm_f16_kernel<false, true, float>,
                         cudaFuncAttributeMaxDynamicSharedMemorySize, GEMM_SMEM);

    conv_all_w_kernel<<<(WT_TOT / 4 + 255) / 256, 256>>>(pw_w, qkv_w, out_w, ff_w, wth);

    // Conv block 0: fused (x + pe) -> resid(out) + LN + dwconv
    ln_dwconv_kernel<true><<<dim3(BB, LL / CTILE), 256>>>(
        x, out, dwouth, conv_ln_g, conv_ln_b, dw_w, dw_b);
    gemm_f16_kernel<true, true, float><<<dim3(HH / 128, MM / 128), 256, GEMM_SMEM>>>(
        dwouth, wth + WT_PW, pw_b, out, out, MM, HH, HH);

    for (int i = 1; i < NCC; i++) {
        ln_dwconv_kernel<false><<<dim3(BB, LL / CTILE), 256>>>(
            out, nullptr, dwouth, conv_ln_g + i * HH, conv_ln_b + i * HH,
            dw_w + i * HH * KW, dw_b + i * HH);
        gemm_f16_kernel<true, true, float><<<dim3(HH / 128, MM / 128), 256, GEMM_SMEM>>>(
            dwouth, wth + WT_PW + (size_t)i * HH * HH, pw_b + i * HH, out, out, MM, HH, HH);
    }

    ln_h_kernel<<<MM, 128>>>(out, normh, att_ln_g, att_ln_b);
    gemm_f16_kernel<false, false, __half><<<dim3(H3 / 128, MM / 128), 256, GEMM_SMEM>>>(
        normh, wth + WT_QKV, qkv_b, (const float*)nullptr, qkvh, MM, H3, HH);

    flash_kernel<<<dim3(BB * NHH, (LL + 63) / 64), 128>>>(qkvh, mask, attouth);

    gemm_f16_kernel<false, true, float><<<dim3(HH / 128, MM / 128), 256, GEMM_SMEM>>>(
        attouth, wth + WT_OUT, out_b, out, out, MM, HH, HH);

    ln_h_kernel<<<MM, 128>>>(out, normh, ff_ln_g, ff_ln_b);
    gemm_f16_kernel<true, true, float><<<dim3(HH / 128, MM / 128), 256, GEMM_SMEM>>>(
        normh, wth + WT_FF, ff_b, out, out, MM, HH, HH);
}

// round 16
// speedup vs baseline: 1.1447x; 1.0154x over previous
#include <cuda_runtime.h>
#include <cuda_fp16.h>
#include <math.h>
#include <stdint.h>

// Problem constants
#define BB   32
#define LL   400
#define HH   512
#define NHH  8
#define DHH  64
#define KW   7
#define NCC  4
#define MM   (BB * LL)      // 12800 tokens
#define H3   (3 * HH)       // 1536

// ---------------------------------------------------------------------------
// Scratch
// ---------------------------------------------------------------------------
__device__ __half g_norm_h [MM * HH];
__device__ __half g_dwout_h[MM * HH];
__device__ __half g_qkv_h  [MM * H3];
__device__ __half g_attout_h[MM * HH];
// fp16 weights: pw | qkv | out | ff
#define WT_PW   0
#define WT_QKV  (NCC * HH * HH)
#define WT_OUT  (WT_QKV + H3 * HH)
#define WT_FF   (WT_OUT + HH * HH)
#define WT_TOT  (WT_FF + HH * HH)
__device__ __half g_wth[WT_TOT];

// ---------------------------------------------------------------------------
// helpers
// ---------------------------------------------------------------------------
__device__ __forceinline__ void mma_f16(float* d, const unsigned* a, const unsigned* b) {
    asm volatile(
        "mma.sync.aligned.m16n8k16.row.col.f32.f16.f16.f32 "
        "{%0,%1,%2,%3}, {%4,%5,%6,%7}, {%8,%9}, {%0,%1,%2,%3};\n"
        : "+f"(d[0]), "+f"(d[1]), "+f"(d[2]), "+f"(d[3])
        : "r"(a[0]), "r"(a[1]), "r"(a[2]), "r"(a[3]), "r"(b[0]), "r"(b[1]));
}

__device__ __forceinline__ void ldsm_x4(unsigned* r, unsigned addr) {
    asm volatile("ldmatrix.sync.aligned.m8n8.x4.shared.b16 {%0,%1,%2,%3}, [%4];"
                 : "=r"(r[0]), "=r"(r[1]), "=r"(r[2]), "=r"(r[3]) : "r"(addr));
}
__device__ __forceinline__ void ldsm_x2(unsigned* r, unsigned addr) {
    asm volatile("ldmatrix.sync.aligned.m8n8.x2.shared.b16 {%0,%1}, [%2];"
                 : "=r"(r[0]), "=r"(r[1]) : "r"(addr));
}

__device__ __forceinline__ void cp_async16(void* smem_dst, const void* gsrc) {
    unsigned sa = (unsigned)__cvta_generic_to_shared(smem_dst);
    asm volatile("cp.async.cg.shared.global [%0], [%1], 16;\n" :: "r"(sa), "l"(gsrc));
}

__device__ __forceinline__ void store2(float* p, float a, float b) {
    *(float2*)p = make_float2(a, b);
}
__device__ __forceinline__ void store2(__half* p, float a, float b) {
    *(__half2*)p = __floats2half2_rn(a, b);
}

// ---------------------------------------------------------------------------
// Weight pre-convert to fp16 (one launch).
// ---------------------------------------------------------------------------
__global__ void conv_all_w_kernel(const float* __restrict__ pw,
                                  const float* __restrict__ qkvw,
                                  const float* __restrict__ ow,
                                  const float* __restrict__ ffw,
                                  __half* __restrict__ out) {
    int i = blockIdx.x * blockDim.x + threadIdx.x;
    const int n_pw  = WT_QKV / 4;
    const int n_qkv = (WT_OUT - WT_QKV) / 4;
    const int n_o   = (WT_FF - WT_OUT) / 4;
    const int n_tot = WT_TOT / 4;
    if (i >= n_tot) return;
    const float* src; int off;
    if (i < n_pw)                     { src = pw;   off = i; }
    else if (i < n_pw + n_qkv)        { src = qkvw; off = i - n_pw; }
    else if (i < n_pw + n_qkv + n_o)  { src = ow;   off = i - n_pw - n_qkv; }
    else                              { src = ffw;  off = i - n_pw - n_qkv - n_o; }
    float4 v = ((const float4*)src)[off];
    ((__half2*)out)[i * 2]     = __floats2half2_rn(v.x, v.y);
    ((__half2*)out)[i * 2 + 1] = __floats2half2_rn(v.z, v.w);
}

// ---------------------------------------------------------------------------
// LayerNorm -> fp16 output. One block/row, 128 thr.
// ---------------------------------------------------------------------------
__global__ void ln_h_kernel(const float* __restrict__ in, __half* __restrict__ out,
                            const float* __restrict__ gw, const float* __restrict__ gb) {
    int row = blockIdx.x;
    int t   = threadIdx.x;  // 128
    const float4* p = (const float4*)(in + (size_t)row * HH);
    float4 v = p[t];

    __shared__ float sh[4];

    float s = v.x + v.y + v.z + v.w;
    #pragma unroll
    for (int o = 16; o > 0; o >>= 1) s += __shfl_down_sync(0xffffffffu, s, o);
    if ((t & 31) == 0) sh[t >> 5] = s;
    __syncthreads();
    float mean = (sh[0] + sh[1] + sh[2] + sh[3]) * (1.0f / HH);
    __syncthreads();

    float dx = v.x - mean, dy = v.y - mean, dz = v.z - mean, dw = v.w - mean;
    float q = dx * dx + dy * dy + dz * dz + dw * dw;
    #pragma unroll
    for (int o = 16; o > 0; o >>= 1) q += __shfl_down_sync(0xffffffffu, q, o);
    if ((t & 31) == 0) sh[t >> 5] = q;
    __syncthreads();
    float var  = (sh[0] + sh[1] + sh[2] + sh[3]) * (1.0f / HH);
    float rstd = rsqrtf(var + 1e-5f);

    float4 g4 = ((const float4*)gw)[t];
    float4 b4 = ((const float4*)gb)[t];
    float ox = dx * rstd * g4.x + b4.x;
    float oy = dy * rstd * g4.y + b4.y;
    float oz = dz * rstd * g4.z + b4.z;
    float ow = dw * rstd * g4.w + b4.w;
    __half2* o2 = (__half2*)(out + (size_t)row * HH);
    o2[t * 2]     = __floats2half2_rn(ox, oy);
    o2[t * 2 + 1] = __floats2half2_rn(oz, ow);
}

// ---------------------------------------------------------------------------
// Fused (optional PE-add) + LayerNorm + depthwise conv (K=7, pad 3).
// LN tile staged in smem as fp16 (conv accumulates fp32 from half2 loads).
// ---------------------------------------------------------------------------
#define CTILE 16
#define CHALO 3
#define CROWS (CTILE + 2 * CHALO)   // 22

template <bool ADDPE>
__global__ void __launch_bounds__(256)
ln_dwconv_kernel(const float* __restrict__ in, float* __restrict__ resid,
                 __half* __restrict__ dwout,
                 const float* __restrict__ gw, const float* __restrict__ gb,
                 const float* __restrict__ w, const float* __restrict__ bias) {
    __shared__ __half sm[CROWS * HH];   // 22528 bytes

    int b    = blockIdx.x;
    int t0   = blockIdx.y * CTILE;
    int tid  = threadIdx.x;
    int warp = tid >> 5;
    int lane = tid & 31;

    for (int rr = warp; rr < CROWS; rr += 8) {
        int l = t0 - CHALO + rr;
        if (l < 0 || l >= LL) {
            // zero 4 halves x 4 chunks per lane (uint2 = 4 halves)
            #pragma unroll
            for (int j = 0; j < 4; j++)
                *(uint2*)&sm[rr * HH + lane * 4 + j * 128] = make_uint2(0u, 0u);
            continue;
        }
        const float4* p = (const float4*)(in + ((size_t)(b * LL + l)) * HH);
        float4 v[4];
        #pragma unroll
        for (int j = 0; j < 4; j++) {
            v[j] = p[lane + j * 32];
            if (ADDPE) {
                int c = lane * 4 + j * 128;
                #pragma unroll
                for (int e = 0; e < 4; e++) {
                    int ch = c + e;
                    float freq = expf(-(float)(ch & ~1) * (9.210340371976184f / (float)HH));
                    float a = (float)l * freq;
                    float pe = (ch & 1) ? cosf(a) : sinf(a);
                    (&v[j].x)[e] += pe;
                }
            }
        }
        if (ADDPE && rr >= CHALO && rr < CHALO + CTILE) {
            float4* rp = (float4*)(resid + ((size_t)(b * LL + l)) * HH);
            #pragma unroll
            for (int j = 0; j < 4; j++) rp[lane + j * 32] = v[j];
        }

        float s = 0.0f;
        #pragma unroll
        for (int j = 0; j < 4; j++) s += v[j].x + v[j].y + v[j].z + v[j].w;
        #pragma unroll
        for (int o = 16; o > 0; o >>= 1) s += __shfl_xor_sync(0xffffffffu, s, o);
        float mean = s * (1.0f / HH);

        float q = 0.0f;
        #pragma unroll
        for (int j = 0; j < 4; j++) {
            float dx = v[j].x - mean, dy = v[j].y - mean;
            float dz = v[j].z - mean, dw = v[j].w - mean;
            q += dx * dx + dy * dy + dz * dz + dw * dw;
        }
        #pragma unroll
        for (int o = 16; o > 0; o >>= 1) q += __shfl_xor_sync(0xffffffffu, q, o);
        float rstd = rsqrtf(q * (1.0f / HH) + 1e-5f);

        #pragma unroll
        for (int j = 0; j < 4; j++) {
            int c = lane * 4 + j * 128;
            float4 g4 = *(const float4*)&gw[c];
            float4 b4 = *(const float4*)&gb[c];
            __half2 h0 = __floats2half2_rn((v[j].x - mean) * rstd * g4.x + b4.x,
                                           (v[j].y - mean) * rstd * g4.y + b4.y);
            __half2 h1 = __floats2half2_rn((v[j].z - mean) * rstd * g4.z + b4.z,
                                           (v[j].w - mean) * rstd * g4.w + b4.w);
            uint2 sv;
            sv.x = *(unsigned*)&h0;
            sv.y = *(unsigned*)&h1;
            *(uint2*)&sm[rr * HH + c] = sv;
        }
    }
    __syncthreads();

    int c0 = tid * 2;
    float wr0[KW], wr1[KW];
    #pragma unroll
    for (int k = 0; k < KW; k++) {
        wr0[k] = w[c0 * KW + k];
        wr1[k] = w[(c0 + 1) * KW + k];
    }
    float bi0 = bias[c0], bi1 = bias[c0 + 1];

    #pragma unroll 4
    for (int r = 0; r < CTILE; r++) {
        float a0 = bi0, a1 = bi1;
        #pragma unroll
        for (int k = 0; k < KW; k++) {
            __half2 xh = *(const __half2*)&sm[(r + k) * HH + c0];
            float2 x = __half22float2(xh);
            a0 += x.x * wr0[k];
            a1 += x.y * wr1[k];
        }
        *(__half2*)&dwout[((size_t)(b * LL + t0 + r)) * HH + c0] =
            __floats2half2_rn(a0, a1);
    }
}

// ---------------------------------------------------------------------------
// fp16 tensor-core GEMM: BM=128, BN=128, BK=32 halves, 3-stage cp.async,
// ldmatrix fragment loads, pad stride 20 words.
// ---------------------------------------------------------------------------
#define GH_ROWW  20
#define GH_SS    (128 * GH_ROWW)
#define GH_NSTG  3
#define GEMM_SMEM (GH_NSTG * GH_SS * 2 * 4)         // 61440 bytes

template <bool RELU, bool RES, typename TOUT>
__global__ void __launch_bounds__(256, 2)
gemm_f16_kernel(const __half* __restrict__ A, const __half* __restrict__ W,
                const float* __restrict__ bias, const float* __restrict__ R,
                TOUT* __restrict__ C, int Md, int Nd, int Kd) {
    extern __shared__ unsigned gsm[];
    unsigned* Asm = gsm;
    unsigned* Bsm = gsm + GH_NSTG * GH_SS;

    int tid  = threadIdx.x;
    int m0   = blockIdx.y * 128;
    int n0   = blockIdx.x * 128;
    int warp = tid >> 5;
    int lane = tid & 31;
    int wm   = (warp >> 2) * 64;
    int wn   = (warp & 3) * 32;
    int lg   = lane >> 2;
    int lq   = lane & 3;

    int lrow = tid >> 2;
    int lchunk = (tid & 3);
    int sw = lrow * GH_ROWW + lchunk * 4;
    int sw2 = (64 + lrow) * GH_ROWW + lchunk * 4;

    int aOff[4], bOff[4];
    #pragma unroll
    for (int mt = 0; mt < 4; mt++)
        aOff[mt] = (wm + mt * 16 + (lane & 15)) * GH_ROWW + ((lane >> 4) * 4);
    #pragma unroll
    for (int nt = 0; nt < 4; nt++)
        bOff[nt] = (wn + nt * 8 + (lane & 7)) * GH_ROWW + (((lane >> 3) & 1) * 4);

    const __half* Ag0 = &A[(size_t)(m0 + lrow)      * Kd + lchunk * 8];
    const __half* Ag1 = &A[(size_t)(m0 + 64 + lrow) * Kd + lchunk * 8];
    const __half* Wg0 = &W[(size_t)(n0 + lrow)      * Kd + lchunk * 8];
    const __half* Wg1 = &W[(size_t)(n0 + 64 + lrow) * Kd + lchunk * 8];

    float acc[4][4][4];
    #pragma unroll
    for (int i = 0; i < 4; i++)
        #pragma unroll
        for (int j = 0; j < 4; j++)
            #pragma unroll
            for (int r = 0; r < 4; r++) acc[i][j][r] = 0.0f;

    #define LOAD_STAGE(s, ko)                                                   \
    {                                                                           \
        unsigned* As_ = Asm + (s) * GH_SS;                                      \
        unsigned* Bs_ = Bsm + (s) * GH_SS;                                      \
        cp_async16(As_ + sw,  Ag0 + (ko));                                      \
        cp_async16(As_ + sw2, Ag1 + (ko));                                      \
        cp_async16(Bs_ + sw,  Wg0 + (ko));                                      \
        cp_async16(Bs_ + sw2, Wg1 + (ko));                                      \
        asm volatile("cp.async.commit_group;\n");                               \
    }

    int nit = Kd >> 5;
    LOAD_STAGE(0, 0);
    if (nit > 1) LOAD_STAGE(1, 32);

    for (int it = 0; it < nit; it++) {
        if (it + 1 < nit)
            asm volatile("cp.async.wait_group 1;\n");
        else
            asm volatile("cp.async.wait_group 0;\n");
        __syncthreads();
        if (it + 2 < nit) LOAD_STAGE((it + 2) % GH_NSTG, (it + 2) << 5);

        int cur = it % GH_NSTG;
        unsigned aBase = (unsigned)__cvta_generic_to_shared(Asm + cur * GH_SS);
        unsigned bBase = (unsigned)__cvta_generic_to_shared(Bsm + cur * GH_SS);

        #pragma unroll
        for (int ks = 0; ks < 2; ks++) {
            int kb = ks * 8;
            unsigned af[4][4], bf[4][2];
            #pragma unroll
            for (int mt = 0; mt < 4; mt++)
                ldsm_x4(af[mt], aBase + (unsigned)(aOff[mt] + kb) * 4u);
            #pragma unroll
            for (int nt = 0; nt < 4; nt++)
                ldsm_x2(bf[nt], bBase + (unsigned)(bOff[nt] + kb) * 4u);
            #pragma unroll
            for (int mt = 0; mt < 4; mt++)
                #pragma unroll
                for (int nt = 0; nt < 4; nt++)
                    mma_f16(acc[mt][nt], af[mt], bf[nt]);
        }
    }
    #undef LOAD_STAGE

    #pragma unroll
    for (int mt = 0; mt < 4; mt++) {
        #pragma unroll
        for (int half = 0; half < 2; half++) {
            int m = m0 + wm + mt * 16 + lg + half * 8;
            #pragma unroll
            for (int nt = 0; nt < 4; nt++) {
                int n = n0 + wn + nt * 8 + 2 * lq;
                float v0 = acc[mt][nt][half * 2 + 0] + bias[n];
                float v1 = acc[mt][nt][half * 2 + 1] + bias[n + 1];
                if (RELU) { v0 = fmaxf(v0, 0.0f); v1 = fmaxf(v1, 0.0f); }
                if (RES)  { v0 += R[(size_t)m * Nd + n]; v1 += R[(size_t)m * Nd + n + 1]; }
                store2(&C[(size_t)m * Nd + n], v0, v1);
            }
        }
    }
}

// ---------------------------------------------------------------------------
// Fused flash attention, fp16 MMA (m16n8k16), online softmax.
// ---------------------------------------------------------------------------
#define FW 36

__global__ void __launch_bounds__(128)
flash_kernel(const __half* __restrict__ qkv, const int* __restrict__ mask,
             __half* __restrict__ attout) {
    __shared__ unsigned Qs [64 * FW];
    __shared__ unsigned KPs[64 * FW];
    __shared__ unsigned Vst[64 * FW];
    __shared__ int msk[64];

    int bh = blockIdx.x;
    int b  = bh >> 3;
    int h  = bh & 7;
    int q0 = blockIdx.y * 64;

    int tid  = threadIdx.x;
    int warp = tid >> 5;
    int lane = tid & 31;
    int wr   = warp * 16;
    int lg   = lane >> 2;
    int lq   = lane & 3;

    const __half2 qsc = __float2half2_rn(0.125f);

    for (int i = tid; i < 512; i += 128) {
        int r  = i >> 3;
        int cw = (i & 7) * 4;
        int qr = q0 + r; if (qr > LL - 1) qr = LL - 1;
        uint4 v = *(const uint4*)&qkv[((size_t)(b * LL + qr)) * H3 + h * DHH + cw * 2];
        __half2 h0 = __hmul2(*(__half2*)&v.x, qsc);
        __half2 h1 = __hmul2(*(__half2*)&v.y, qsc);
        __half2 h2 = __hmul2(*(__half2*)&v.z, qsc);
        __half2 h3 = __hmul2(*(__half2*)&v.w, qsc);
        uint4 sv;
        sv.x = *(unsigned*)&h0; sv.y = *(unsigned*)&h1;
        sv.z = *(unsigned*)&h2; sv.w = *(unsigned*)&h3;
        *(uint4*)&Qs[r * FW + cw] = sv;
    }

    float oacc[8][4];
    #pragma unroll
    for (int nt = 0; nt < 8; nt++)
        #pragma unroll
        for (int r2 = 0; r2 < 4; r2++) oacc[nt][r2] = 0.0f;
    float m0 = -1e30f, m1 = -1e30f, l0 = 0.0f, l1 = 0.0f;

    for (int kt = 0; kt < LL; kt += 64) {
        __syncthreads();

        for (int i = tid; i < 512; i += 128) {
            int r  = i >> 3;
            int cw = (i & 7) * 4;
            int kr = kt + r; if (kr > LL - 1) kr = LL - 1;
            const __half* base = &qkv[((size_t)(b * LL + kr)) * H3 + h * DHH + cw * 2];
            uint4 kv = *(const uint4*)(base + HH);
            *(uint4*)&KPs[r * FW + cw] = kv;
            uint4 vv = *(const uint4*)(base + 2 * HH);
            const __half* vh = (const __half*)&vv;
            __half* Vh = (__half*)Vst;
            #pragma unroll
            for (int j = 0; j < 8; j++)
                Vh[(cw * 2 + j) * (FW * 2) + r] = vh[j];
        }
        if (tid < 64) msk[tid] = (kt + tid < LL) ? mask[b * LL + kt + tid] : 0;
        __syncthreads();

        float sacc[8][4];
        #pragma unroll
        for (int nt = 0; nt < 8; nt++)
            #pragma unroll
            for (int r2 = 0; r2 < 4; r2++) sacc[nt][r2] = 0.0f;

        #pragma unroll
        for (int ks = 0; ks < 4; ks++) {
            int kb = ks * 8;
            unsigned af[4];
            af[0] = Qs[(wr + lg)     * FW + kb + lq];
            af[1] = Qs[(wr + lg + 8) * FW + kb + lq];
            af[2] = Qs[(wr + lg)     * FW + kb + lq + 4];
            af[3] = Qs[(wr + lg + 8) * FW + kb + lq + 4];
            #pragma unroll
            for (int nt = 0; nt < 8; nt++) {
                unsigned bf[2];
                bf[0] = KPs[(nt * 8 + lg) * FW + kb + lq];
                bf[1] = KPs[(nt * 8 + lg) * FW + kb + lq + 4];
                mma_f16(sacc[nt], af, bf);
            }
        }

        float rmax0 = -1e30f, rmax1 = -1e30f;
        #pragma unroll
        for (int nt = 0; nt < 8; nt++) {
            #pragma unroll
            for (int j = 0; j < 2; j++) {
                int kl = nt * 8 + 2 * lq + j;
                bool ok = (kt + kl < LL) && (msk[kl] > 0);
                if (!ok) { sacc[nt][j] = -1e30f; sacc[nt][2 + j] = -1e30f; }
                rmax0 = fmaxf(rmax0, sacc[nt][j]);
                rmax1 = fmaxf(rmax1, sacc[nt][2 + j]);
            }
        }
        #pragma unroll
        for (int o = 1; o <= 2; o <<= 1) {
            rmax0 = fmaxf(rmax0, __shfl_xor_sync(0xffffffffu, rmax0, o));
            rmax1 = fmaxf(rmax1, __shfl_xor_sync(0xffffffffu, rmax1, o));
        }

        float m0n = fmaxf(m0, rmax0);
        float m1n = fmaxf(m1, rmax1);
        float alpha0 = __expf(m0 - m0n);
        float alpha1 = __expf(m1 - m1n);
        m0 = m0n; m1 = m1n;

        float rs0 = 0.0f, rs1 = 0.0f;
        #pragma unroll
        for (int nt = 0; nt < 8; nt++) {
            #pragma unroll
            for (int j = 0; j < 2; j++) {
                float p0 = __expf(sacc[nt][j] - m0);
                float p1 = __expf(sacc[nt][2 + j] - m1);
                sacc[nt][j] = p0;     rs0 += p0;
                sacc[nt][2 + j] = p1; rs1 += p1;
            }
        }
        #pragma unroll
        for (int o = 1; o <= 2; o <<= 1) {
            rs0 += __shfl_xor_sync(0xffffffffu, rs0, o);
            rs1 += __shfl_xor_sync(0xffffffffu, rs1, o);
        }
        l0 = l0 * alpha0 + rs0;
        l1 = l1 * alpha1 + rs1;

        #pragma unroll
        for (int nt = 0; nt < 8; nt++) {
            oacc[nt][0] *= alpha0; oacc[nt][1] *= alpha0;
            oacc[nt][2] *= alpha1; oacc[nt][3] *= alpha1;
        }

        __syncthreads();

        #pragma unroll
        for (int nt = 0; nt < 8; nt++) {
            __half2 p01 = __floats2half2_rn(sacc[nt][0], sacc[nt][1]);
            __half2 p23 = __floats2half2_rn(sacc[nt][2], sacc[nt][3]);
            KPs[(wr + lg)     * FW + nt * 4 + lq] = *(unsigned*)&p01;
            KPs[(wr + lg + 8) * FW + nt * 4 + lq] = *(unsigned*)&p23;
        }
        __syncwarp();

        #pragma unroll
        for (int ks = 0; ks < 4; ks++) {
            int kb = ks * 8;
            unsigned af[4];
            af[0] = KPs[(wr + lg)     * FW + kb + lq];
            af[1] = KPs[(wr + lg + 8) * FW + kb + lq];
            af[2] = KPs[(wr + lg)     * FW + kb + lq + 4];
            af[3] = KPs[(wr + lg + 8) * FW + kb + lq + 4];
            #pragma unroll
            for (int nt = 0; nt < 8; nt++) {
                unsigned bf[2];
                bf[0] = Vst[(nt * 8 + lg) * FW + kb + lq];
                bf[1] = Vst[(nt * 8 + lg) * FW + kb + lq + 4];
                mma_f16(oacc[nt], af, bf);
            }
        }
    }

    float inv0 = 1.0f / fmaxf(l0, 1e-30f);
    float inv1 = 1.0f / fmaxf(l1, 1e-30f);
    int r0 = q0 + wr + lg;
    int r1 = r0 + 8;
    #pragma unroll
    for (int nt = 0; nt < 8; nt++) {
        int c = nt * 8 + 2 * lq;
        if (r0 < LL)
            *(__half2*)&attout[((size_t)(b * LL + r0)) * HH + h * DHH + c] =
                __floats2half2_rn(oacc[nt][0] * inv0, oacc[nt][1] * inv0);
        if (r1 < LL)
            *(__half2*)&attout[((size_t)(b * LL + r1)) * HH + h * DHH + c] =
                __floats2half2_rn(oacc[nt][2] * inv1, oacc[nt][3] * inv1);
    }
}

// ---------------------------------------------------------------------------
// Launch
// ---------------------------------------------------------------------------
extern "C" void kernel_launch(void* const* d_in, const int* in_sizes, int n_in,
                              void* d_out, int out_size) {
    const float* x         = (const float*)d_in[0];
    const int*   mask      = (const int*)  d_in[1];
    const float* conv_ln_g = (const float*)d_in[2];
    const float* conv_ln_b = (const float*)d_in[3];
    const float* dw_w      = (const float*)d_in[4];
    const float* dw_b      = (const float*)d_in[5];
    const float* pw_w      = (const float*)d_in[6];
    const float* pw_b      = (const float*)d_in[7];
    const float* att_ln_g  = (const float*)d_in[8];
    const float* att_ln_b  = (const float*)d_in[9];
    const float* qkv_w     = (const float*)d_in[10];
    const float* qkv_b     = (const float*)d_in[11];
    const float* out_w     = (const float*)d_in[12];
    const float* out_b     = (const float*)d_in[13];
    const float* ff_ln_g   = (const float*)d_in[14];
    const float* ff_ln_b   = (const float*)d_in[15];
    const float* ff_w      = (const float*)d_in[16];
    const float* ff_b      = (const float*)d_in[17];
    float* out = (float*)d_out;

    __half *normh, *dwouth, *qkvh, *attouth, *wth;
    cudaGetSymbolAddress((void**)&normh,   g_norm_h);
    cudaGetSymbolAddress((void**)&dwouth,  g_dwout_h);
    cudaGetSymbolAddress((void**)&qkvh,    g_qkv_h);
    cudaGetSymbolAddress((void**)&attouth, g_attout_h);
    cudaGetSymbolAddress((void**)&wth,     g_wth);

    cudaFuncSetAttribute(gemm_f16_kernel<true, true, float>,
                         cudaFuncAttributeMaxDynamicSharedMemorySize, GEMM_SMEM);
    cudaFuncSetAttribute(gemm_f16_kernel<false, false, __half>,
                         cudaFuncAttributeMaxDynamicSharedMemorySize, GEMM_SMEM);
    cudaFuncSetAttribute(gemm_f16_kernel<false, true, float>,
                         cudaFuncAttributeMaxDynamicSharedMemorySize, GEMM_SMEM);

    conv_all_w_kernel<<<(WT_TOT / 4 + 255) / 256, 256>>>(pw_w, qkv_w, out_w, ff_w, wth);

    // Conv block 0: fused (x + pe) -> resid(out) + LN + dwconv
    ln_dwconv_kernel<true><<<dim3(BB, LL / CTILE), 256>>>(
        x, out, dwouth, conv_ln_g, conv_ln_b, dw_w, dw_b);
    gemm_f16_kernel<true, true, float><<<dim3(HH / 128, MM / 128), 256, GEMM_SMEM>>>(
        dwouth, wth + WT_PW, pw_b, out, out, MM, HH, HH);

    for (int i = 1; i < NCC; i++) {
        ln_dwconv_kernel<false><<<dim3(BB, LL / CTILE), 256>>>(
            out, nullptr, dwouth, conv_ln_g + i * HH, conv_ln_b + i * HH,
            dw_w + i * HH * KW, dw_b + i * HH);
        gemm_f16_kernel<true, true, float><<<dim3(HH / 128, MM / 128), 256, GEMM_SMEM>>>(
            dwouth, wth + WT_PW + (size_t)i * HH * HH, pw_b + i * HH, out, out, MM, HH, HH);
    }

    ln_h_kernel<<<MM, 128>>>(out, normh, att_ln_g, att_ln_b);
    gemm_f16_kernel<false, false, __half><<<dim3(H3 / 128, MM / 128), 256, GEMM_SMEM>>>(
        normh, wth + WT_QKV, qkv_b, (const float*)nullptr, qkvh, MM, H3, HH);

    flash_kernel<<<dim3(BB * NHH, (LL + 63) / 64), 128>>>(qkvh, mask, attouth);

    gemm_f16_kernel<false, true, float><<<dim3(HH / 128, MM / 128), 256, GEMM_SMEM>>>(
        attouth, wth + WT_OUT, out_b, out, out, MM, HH, HH);

    ln_h_kernel<<<MM, 128>>>(out, normh, ff_ln_g, ff_ln_b);
    gemm_f16_kernel<true, true, float><<<dim3(HH / 128, MM / 128), 256, GEMM_SMEM>>>(
        normh, wth + WT_FF, ff_b, out, out, MM, HH, HH);
}